// round 13
// baseline (speedup 1.0000x reference)
#include <cuda_runtime.h>
#include <cuda_fp16.h>
#include <math.h>
#include <stdint.h>

#define VV 50000
#define EE 512
#define HH 512
#define BB 128
#define SS 256
#define OOV 12
#define VEXT (VV + OOV)   // 50012

// ---------------- fp32 scratch ----------------
// zeroed range: [OFF_PREV, NZEND) = prev, gi, gh, satt (atomic targets)
#define OFF_PREV   0
#define OFF_GI     (OFF_PREV + BB*HH)
#define OFF_GH     (OFF_GI + BB*3*HH)
#define OFF_SATT   (OFF_GH + BB*3*HH)
#define NZEND      (OFF_SATT + BB*HH)
#define NZ         NZEND
#define OFF_STATE  NZEND
#define OFF_ENERGY (OFF_STATE + BB*HH)
#define OFF_Y      (OFF_ENERGY + BB*SS)
#define OFF_SCOREG (OFF_Y + BB*2*HH)
#define OFF_SCOREC (OFF_SCOREG + (size_t)BB*VV)
#define OFF_PROBC  (OFF_SCOREC + BB*SS)
#define OFF_INVZ   (OFF_PROBC + BB*SS)
#define OFF_Z      (OFF_INVZ + BB)
#define OFF_PCSUM  (OFF_Z + BB)
#define SCRATCH_FLOATS (OFF_PCSUM + 64)

__device__ float g_scratch[SCRATCH_FLOATS];

// ---------------- helpers ----------------
__device__ __forceinline__ uint32_t smem_u32(const void* p) {
    uint32_t a;
    asm("{ .reg .u64 t; cvta.to.shared.u64 t, %1; cvt.u32.u64 %0, t; }"
        : "=r"(a) : "l"(p));
    return a;
}
static __device__ __forceinline__ uint32_t SWZ(uint32_t o) {
    return o ^ ((o >> 3) & 0x70u);
}
__device__ __forceinline__ void cpa16(uint32_t dst, const void* src, int srcsize) {
    asm volatile("cp.async.cg.shared.global [%0], [%1], 16, %2;"
                 :: "r"(dst), "l"(src), "r"(srcsize) : "memory");
}
__device__ __forceinline__ void cpa_commit() {
    asm volatile("cp.async.commit_group;" ::: "memory");
}
__device__ __forceinline__ void cpa_wait0() {
    asm volatile("cp.async.wait_group 0;" ::: "memory");
}
__device__ __forceinline__ void ldm_x4(uint32_t& r0, uint32_t& r1,
                                       uint32_t& r2, uint32_t& r3, uint32_t a) {
    asm volatile("ldmatrix.sync.aligned.m8n8.x4.shared.b16 {%0,%1,%2,%3}, [%4];"
                 : "=r"(r0), "=r"(r1), "=r"(r2), "=r"(r3) : "r"(a));
}
__device__ __forceinline__ void mma16816(float& c0, float& c1, float& c2, float& c3,
                                         uint32_t a0, uint32_t a1, uint32_t a2,
                                         uint32_t a3, uint32_t b0, uint32_t b1) {
    asm volatile("mma.sync.aligned.m16n8k16.row.col.f32.f16.f16.f32 "
                 "{%0,%1,%2,%3}, {%4,%5,%6,%7}, {%8,%9}, {%0,%1,%2,%3};"
                 : "+f"(c0), "+f"(c1), "+f"(c2), "+f"(c3)
                 : "r"(a0), "r"(a1), "r"(a2), "r"(a3), "r"(b0), "r"(b1));
}
// accurate-enough fast tanh: 1 - 2/(exp(2x)+1); abs err ~1e-7
__device__ __forceinline__ float fast_tanh(float x) {
    float e = __expf(2.f * x);
    return 1.f - __fdividef(2.f, e + 1.f);
}

// ============ HMMA core: fp32 in, 3-term split, convert/MMA overlapped ======
// Block tile (32*MI rows) x (32*NJ cols). k-chunk = 32 fp32 cols.
// mode 0: outS = D + add_s[n]
// mode 1: atomicAdd(outv[row0+m], sum_n tanh(D + add_s[n]) * wv_s[n])
// mode 2: outS = exp(D + add_s[n]); atomicAdd(outv[row0+m], row-sum of exp)
#define V4_DYN (199680 + 1024)   // max over instantiations (MI=4, NJ=8)

template <int NJ, int MI>
__device__ __forceinline__ void hmma_core(
    char* smem,
    const float* __restrict__ A, int lda, int K,
    const float* __restrict__ B, int ldb, int bcol, int Nrows,
    int mode,
    const float* __restrict__ addg, int add_per_b, int Ntot,
    const float* __restrict__ wvg, int wv_per_b,
    float* __restrict__ outS, int ldout,
    float* __restrict__ outv,
    int row0, int n0)
{
    constexpr int ABYTES = MI * 4096;
    constexpr int BBYTES = NJ * 4096;
    constexpr int O_SB = 2 * ABYTES;
    constexpr int O_HA = 2 * ABYTES + 2 * BBYTES;
    constexpr int O_HB = 4 * ABYTES + 2 * BBYTES;
    constexpr int O_ADD = 4 * ABYTES + 4 * BBYTES;
    constexpr int O_WV = O_ADD + NJ * 128;
    constexpr int TOT = MI + NJ;

    const uint32_t sb = smem_u32(smem);
    const int tid = threadIdx.x, wid = tid >> 5, lid = tid & 31;
    const int b    = row0 >> 8;
    const int wm0  = (wid >> 2) * (16 * MI);
    const int wn0  = (wid & 3) * (NJ * 8);

    float* add_s = (float*)(smem + O_ADD);
    float* wv_s  = (float*)(smem + O_WV);
    if (tid < NJ * 32) {
        int gn = n0 + tid;
        if (mode != 1) {
            add_s[tid] = (gn < Nrows) ? addg[gn] : 0.f;
        } else {
            add_s[tid] = add_per_b ? addg[(size_t)b * Ntot + gn] : addg[gn];
            wv_s[tid]  = wv_per_b ? wvg[(size_t)b * Ntot + gn] : wvg[gn];
        }
    }

    const int nc = K >> 5;

    auto issue = [&](int c, int par) {
        int k0 = c << 5;
#pragma unroll
        for (int i = 0; i < MI; i++) {
            int u = tid + i * 256;
            int r = u >> 3, b16 = u & 7;
            cpa16(sb + par * ABYTES + (uint32_t)(r * 128 + b16 * 16),
                  &A[(size_t)(row0 + r) * lda + k0 + b16 * 4], 16);
        }
#pragma unroll
        for (int i = 0; i < NJ; i++) {
            int u = tid + i * 256;
            int r = u >> 3, b16 = u & 7;
            int gr = n0 + r;
            int ok = (gr < Nrows) ? 16 : 0;
            int grc = (gr < Nrows) ? gr : 0;
            cpa16(sb + O_SB + par * BBYTES + (uint32_t)(r * 128 + b16 * 16),
                  &B[(size_t)grc * ldb + bcol + k0 + b16 * 4], ok);
        }
        cpa_commit();
    };

    auto conv_range = [&](int par, int i0, int i1) {
        for (int i = i0; i < i1; i++) {
            int stage_off, h_off, idx;
            if (i < MI) {
                idx = tid + i * 256;
                stage_off = par * ABYTES;
                h_off = O_HA + par * ABYTES;
            } else {
                idx = tid + (i - MI) * 256;
                stage_off = O_SB + par * BBYTES;
                h_off = O_HB + par * BBYTES;
            }
            int r = idx >> 3, c4 = idx & 7;
            float4 v = *(const float4*)(smem + stage_off + r * 128 + c4 * 16);
            __half2 h01 = __float22half2_rn(make_float2(v.x, v.y));
            __half2 h23 = __float22half2_rn(make_float2(v.z, v.w));
            float2 f01 = __half22float2(h01);
            float2 f23 = __half22float2(h23);
            __half2 l01 = __float22half2_rn(make_float2(v.x - f01.x, v.y - f01.y));
            __half2 l23 = __float22half2_rn(make_float2(v.z - f23.x, v.w - f23.y));
            uint2 hv = make_uint2(*(uint32_t*)&h01, *(uint32_t*)&h23);
            uint2 lv = make_uint2(*(uint32_t*)&l01, *(uint32_t*)&l23);
            *(uint2*)(smem + h_off + SWZ((uint32_t)(r * 128 + c4 * 8))) = hv;
            *(uint2*)(smem + h_off + SWZ((uint32_t)(r * 128 + 64 + c4 * 8))) = lv;
        }
    };

    float cacc[MI][NJ][4];
#pragma unroll
    for (int mi = 0; mi < MI; mi++)
#pragma unroll
        for (int nj = 0; nj < NJ; nj++)
#pragma unroll
            for (int f = 0; f < 4; f++) cacc[mi][nj][f] = 0.f;

    const int a_row  = wm0 + (lid & 15);
    const int a_csel = ((lid >> 4) & 1) * 16;
    const int b_rowo = (lid & 7) + ((lid >> 4) & 1) * 8;
    const int b_csel = ((lid >> 3) & 1) * 16;

    issue(0, 0);
    cpa_wait0();
    conv_range(0, 0, TOT);
    if (nc > 1) issue(1, 1);
    __syncthreads();

    for (int c = 0; c < nc; c++) {
        const int par = c & 1;
        const bool more = (c + 1 < nc);
        if (more) {
            cpa_wait0();
            if (c + 2 < nc) issue(c + 2, par);
        }
        const uint32_t ha = sb + O_HA + par * ABYTES;
        const uint32_t hb = sb + O_HB + par * BBYTES;
#pragma unroll
        for (int sg = 0; sg < 6; sg++) {
            const int t = sg >> 1, k16 = sg & 1;
            const int aoff = (t == 1) ? 64 : 0;
            const int boff = (t == 2) ? 64 : 0;
            uint32_t a[MI][4];
#pragma unroll
            for (int mi = 0; mi < MI; mi++) {
                uint32_t addr = ha + SWZ((uint32_t)((a_row + mi * 16) * 128 +
                                                    aoff + k16 * 32 + a_csel));
                ldm_x4(a[mi][0], a[mi][1], a[mi][2], a[mi][3], addr);
            }
            uint32_t bf[NJ][2];
#pragma unroll
            for (int nj2 = 0; nj2 < NJ / 2; nj2++) {
                uint32_t addr = hb + SWZ((uint32_t)((wn0 + nj2 * 16 + b_rowo) * 128 +
                                                    boff + k16 * 32 + b_csel));
                ldm_x4(bf[2 * nj2][0], bf[2 * nj2][1],
                       bf[2 * nj2 + 1][0], bf[2 * nj2 + 1][1], addr);
            }
            if (more) conv_range(par ^ 1, (TOT * sg) / 6, (TOT * (sg + 1)) / 6);
#pragma unroll
            for (int mi = 0; mi < MI; mi++)
#pragma unroll
                for (int nj = 0; nj < NJ; nj++)
                    mma16816(cacc[mi][nj][0], cacc[mi][nj][1],
                             cacc[mi][nj][2], cacc[mi][nj][3],
                             a[mi][0], a[mi][1], a[mi][2], a[mi][3],
                             bf[nj][0], bf[nj][1]);
        }
        if (more) __syncthreads();
    }

    const int rA = wm0 + (lid >> 2);
    const int lcol = wn0 + 2 * (lid & 3);
    if (mode == 0) {
#pragma unroll
        for (int mi = 0; mi < MI; mi++) {
#pragma unroll
            for (int nj = 0; nj < NJ; nj++) {
                int lc = lcol + nj * 8;
                int n = n0 + lc;
                if (n < Nrows) {
                    int r0r = row0 + rA + mi * 16;
                    float2 v0 = make_float2(cacc[mi][nj][0] + add_s[lc],
                                            cacc[mi][nj][1] + add_s[lc + 1]);
                    float2 v1 = make_float2(cacc[mi][nj][2] + add_s[lc],
                                            cacc[mi][nj][3] + add_s[lc + 1]);
                    *(float2*)&outS[(size_t)r0r * ldout + n] = v0;
                    *(float2*)&outS[(size_t)(r0r + 8) * ldout + n] = v1;
                }
            }
        }
    } else if (mode == 2) {
        // exp + store + per-row sums (no-shift softmax)
#pragma unroll
        for (int mi = 0; mi < MI; mi++) {
            float s0 = 0.f, s1 = 0.f;
#pragma unroll
            for (int nj = 0; nj < NJ; nj++) {
                int lc = lcol + nj * 8;
                int n = n0 + lc;
                if (n < Nrows) {
                    float e0 = __expf(cacc[mi][nj][0] + add_s[lc]);
                    float e1 = __expf(cacc[mi][nj][1] + add_s[lc + 1]);
                    float e2 = __expf(cacc[mi][nj][2] + add_s[lc]);
                    float e3 = __expf(cacc[mi][nj][3] + add_s[lc + 1]);
                    int r0r = row0 + rA + mi * 16;
                    *(float2*)&outS[(size_t)r0r * ldout + n] = make_float2(e0, e1);
                    *(float2*)&outS[(size_t)(r0r + 8) * ldout + n] = make_float2(e2, e3);
                    s0 += e0 + e1;
                    s1 += e2 + e3;
                }
            }
            s0 += __shfl_xor_sync(0xffffffffu, s0, 1);
            s0 += __shfl_xor_sync(0xffffffffu, s0, 2);
            s1 += __shfl_xor_sync(0xffffffffu, s1, 1);
            s1 += __shfl_xor_sync(0xffffffffu, s1, 2);
            if ((lid & 3) == 0) {
                atomicAdd(&outv[row0 + rA + mi * 16], s0);
                atomicAdd(&outv[row0 + rA + mi * 16 + 8], s1);
            }
        }
    } else {
#pragma unroll
        for (int mi = 0; mi < MI; mi++) {
            float p0 = 0.f, p1 = 0.f;
#pragma unroll
            for (int nj = 0; nj < NJ; nj++) {
                int lc = lcol + nj * 8;
                float ad0 = add_s[lc], ad1 = add_s[lc + 1];
                float w0 = wv_s[lc],  w1 = wv_s[lc + 1];
                p0 += fast_tanh(cacc[mi][nj][0] + ad0) * w0
                    + fast_tanh(cacc[mi][nj][1] + ad1) * w1;
                p1 += fast_tanh(cacc[mi][nj][2] + ad0) * w0
                    + fast_tanh(cacc[mi][nj][3] + ad1) * w1;
            }
            p0 += __shfl_xor_sync(0xffffffffu, p0, 1);
            p0 += __shfl_xor_sync(0xffffffffu, p0, 2);
            p1 += __shfl_xor_sync(0xffffffffu, p1, 1);
            p1 += __shfl_xor_sync(0xffffffffu, p1, 2);
            if ((lid & 3) == 0) {
                atomicAdd(&outv[row0 + rA + mi * 16], p0);
                atomicAdd(&outv[row0 + rA + mi * 16 + 8], p1);
            }
        }
    }
}

// ---- energy GEMM: M-tile 64 (MI=2) for wave packing; 1024 blocks ----
__global__ __launch_bounds__(256)
void hmma_energy(const float* __restrict__ enc,
                 const float* __restrict__ attnW,
                 const float* __restrict__ satt,
                 const float* __restrict__ attnv,
                 float* __restrict__ energy)
{
    extern __shared__ char smem_raw[];
    char* smem = (char*)(((uintptr_t)smem_raw + 1023) & ~(uintptr_t)1023);
    hmma_core<8, 2>(smem, enc, 512, 512, attnW, 1024, 512, 512, 1,
                    satt, 1, 512, attnv, 0, nullptr, 0, energy,
                    blockIdx.x * 64, blockIdx.y * 256);
}

// ---- merged score_g(exp) + score_c GEMM (MI=4) ----
#define NT_G 196
#define NT_C 1024
__global__ __launch_bounds__(256)
void hmma_scores(const float* __restrict__ yv,
                 const float* __restrict__ Wo, const float* __restrict__ Wob,
                 const float* __restrict__ enc,
                 const float* __restrict__ Wc, const float* __restrict__ Wcb,
                 float* __restrict__ scoregE, float* __restrict__ zrow,
                 float* __restrict__ scorec)
{
    extern __shared__ char smem_raw[];
    char* smem = (char*)(((uintptr_t)smem_raw + 1023) & ~(uintptr_t)1023);
    int tile = blockIdx.x;
    if (tile < NT_G) {
        hmma_core<8, 4>(smem, yv, 1024, 1024, Wo, 1024, 0, VV, 2,
                        Wob, 0, 0, nullptr, 0, scoregE, VV, zrow,
                        0, tile * 256);
    } else {
        int t2 = tile - NT_G;
        hmma_core<8, 4>(smem, enc, 512, 512, Wc, 512, 0, 1024, 1,
                        Wcb, 0, 1024, yv, 1, nullptr, 0, scorec,
                        (t2 >> 2) * 128, (t2 & 3) * 256);
    }
}

// ================= FFMA2 small GEMM =================
__device__ __forceinline__ void ffma2(unsigned long long &c,
                                      unsigned long long a,
                                      unsigned long long b) {
    asm("fma.rn.f32x2 %0, %1, %2, %0;" : "+l"(c) : "l"(a), "l"(b));
}
struct __align__(16) ull2 { unsigned long long x, y; };
__device__ __forceinline__ float f2lo(unsigned long long v) {
    return __uint_as_float((unsigned int)v);
}
__device__ __forceinline__ float f2hi(unsigned long long v) {
    return __uint_as_float((unsigned int)(v >> 32));
}
__device__ __forceinline__ unsigned long long dupf(float v) {
    unsigned int u = __float_as_uint(v);
    unsigned long long r;
    asm("mov.b64 %0, {%1, %1};" : "=l"(r) : "r"(u));
    return r;
}
#define K16_FFMA2_LOOP(acc, Asm, Wsm, ty, tx)                                 \
    _Pragma("unroll")                                                         \
    for (int kk = 0; kk < 16; kk++) {                                         \
        ull2 a01 = *(const ull2*)&Asm[kk][(ty) * 8];                          \
        ull2 a23 = *(const ull2*)&Asm[kk][(ty) * 8 + 4];                      \
        float4 wq = *(const float4*)&Wsm[kk][(tx) * 4];                       \
        unsigned long long w0 = dupf(wq.x), w1 = dupf(wq.y);                  \
        unsigned long long w2 = dupf(wq.z), w3 = dupf(wq.w);                  \
        ffma2(acc[0][0], a01.x, w0); ffma2(acc[0][1], a01.x, w1);             \
        ffma2(acc[0][2], a01.x, w2); ffma2(acc[0][3], a01.x, w3);             \
        ffma2(acc[1][0], a01.y, w0); ffma2(acc[1][1], a01.y, w1);             \
        ffma2(acc[1][2], a01.y, w2); ffma2(acc[1][3], a01.y, w3);             \
        ffma2(acc[2][0], a23.x, w0); ffma2(acc[2][1], a23.x, w1);             \
        ffma2(acc[2][2], a23.x, w2); ffma2(acc[2][3], a23.x, w3);             \
        ffma2(acc[3][0], a23.y, w0); ffma2(acc[3][1], a23.y, w1);             \
        ffma2(acc[3][2], a23.y, w2); ffma2(acc[3][3], a23.y, w3);             \
    }

__device__ __forceinline__ void gemm128_core(
    const float* __restrict__ A, int lda, const int* __restrict__ aidx,
    const float* __restrict__ W, int ldw, const float* __restrict__ bias,
    float* __restrict__ C, int N, int n0, int ks, int kl, bool addbias)
{
    __shared__ float Asm[16][132];
    __shared__ float Wsm[16][68];
    const int tid = threadIdx.x;
    const int ty = tid >> 4, tx = tid & 15;
    const int am  = tid >> 2;
    const int akv = (tid & 3) << 2;

    unsigned long long acc[4][4];
#pragma unroll
    for (int i = 0; i < 4; i++)
#pragma unroll
        for (int j = 0; j < 4; j++) acc[i][j] = 0ull;

    for (int k0 = ks; k0 < ks + kl; k0 += 16) {
        __syncthreads();
#pragma unroll
        for (int r = 0; r < 2; r++) {
            int m = am + r * 64;
            long arow = aidx ? (long)aidx[m] : (long)m;
            float4 v = *(const float4*)&A[arow * lda + k0 + akv];
            Asm[akv+0][m] = v.x; Asm[akv+1][m] = v.y;
            Asm[akv+2][m] = v.z; Asm[akv+3][m] = v.w;
        }
        {
            float4 v = *(const float4*)&W[(size_t)(n0 + am) * ldw + k0 + akv];
            Wsm[akv+0][am] = v.x; Wsm[akv+1][am] = v.y;
            Wsm[akv+2][am] = v.z; Wsm[akv+3][am] = v.w;
        }
        __syncthreads();
        K16_FFMA2_LOOP(acc, Asm, Wsm, ty, tx)
    }
#pragma unroll
    for (int r2 = 0; r2 < 4; r2++) {
#pragma unroll
        for (int j = 0; j < 4; j++) {
            int n = n0 + tx * 4 + j;
            float bsum = (addbias && bias) ? bias[n] : 0.f;
            int m0 = ty * 8 + 2 * r2;
            atomicAdd(&C[(size_t)m0 * N + n],       f2lo(acc[r2][j]) + bsum);
            atomicAdd(&C[(size_t)(m0 + 1) * N + n], f2hi(acc[r2][j]) + bsum);
        }
    }
}

__global__ __launch_bounds__(256)
void gemm128_splitk(const float* __restrict__ A, int lda,
                    const float* __restrict__ W, int ldw,
                    const float* __restrict__ bias,
                    float* __restrict__ C, int N, int Ktot)
{
    int kl = Ktot / gridDim.y;
    gemm128_core(A, lda, nullptr, W, ldw, bias, C, N,
                 blockIdx.x * 64, blockIdx.y * kl, kl, blockIdx.y == 0);
}

// merged: prev = prev_state@Ws^T + Ws_b  AND  gi = embed[idx]@Wih[:, :E]^T + bih
__global__ __launch_bounds__(256)
void gemm_chain1(const float* __restrict__ prev_state,
                 const float* __restrict__ Ws_w, const float* __restrict__ Ws_b,
                 float* __restrict__ prev,
                 const int* __restrict__ input_idx,
                 const float* __restrict__ embed_table,
                 const float* __restrict__ gru_Wih,
                 const float* __restrict__ gru_bih,
                 float* __restrict__ gi)
{
    int bx = blockIdx.x;
    if (bx < 64) {
        int n0 = (bx & 7) * 64, kb = bx >> 3;
        gemm128_core(prev_state, HH, nullptr, Ws_w, HH, Ws_b, prev, HH,
                     n0, kb * 64, 64, kb == 0);
    } else {
        bx -= 64;
        int n0 = (bx % 24) * 64, kb = bx / 24;
        gemm128_core(embed_table, EE, input_idx, gru_Wih, EE + HH, gru_bih,
                     gi, 3 * HH, n0, kb * 64, 64, kb == 0);
    }
}

// zero split-K accumulators + energy + scorec + zrow/invz/pcsum (one launch)
__global__ __launch_bounds__(256)
void zero_all(float* __restrict__ base, float* __restrict__ energy,
              float* __restrict__ scorec, float* __restrict__ tailz)
{
    int i = blockIdx.x * 256 + threadIdx.x;
    if (i < NZ) base[i] = 0.f;
    if (i < BB * SS) { energy[i] = 0.f; scorec[i] = 0.f; }
    if (i < 2 * BB + 1) tailz[i] = 0.f;   // invz, zrow, pcsum
}

__global__ __launch_bounds__(256)
void gru_kernel(const float* __restrict__ gi, const float* __restrict__ gh,
                const float* __restrict__ prev,
                float* __restrict__ state, float* __restrict__ y,
                float* __restrict__ out_state)
{
    int i = blockIdx.x * 256 + threadIdx.x;
    int b = i / HH, h = i - b * HH;
    const float* gib = gi + b * 3 * HH;
    const float* ghb = gh + b * 3 * HH;
    float i_r = gib[h],          h_r = ghb[h];
    float i_z = gib[HH + h],     h_z = ghb[HH + h];
    float i_n = gib[2 * HH + h], h_n = ghb[2 * HH + h];
    float r = 1.f / (1.f + expf(-(i_r + h_r)));
    float z = 1.f / (1.f + expf(-(i_z + h_z)));
    float n = tanhf(i_n + r * h_n);
    float st = (1.f - z) * n + z * prev[i];
    state[i] = st;
    y[b * (2 * HH) + h] = st;
    out_state[i] = st;
}

// fused attention softmax + context
__global__ __launch_bounds__(512)
void softmax_context(const float* __restrict__ e, const float* __restrict__ enc,
                     float* __restrict__ y)
{
    int b = blockIdx.x, t = threadIdx.x;
    __shared__ float sm[256];
    __shared__ float c[256];
    float x = 0.f;
    if (t < 256) { x = e[b * SS + t]; sm[t] = x; }
    __syncthreads();
    for (int o = 128; o > 0; o >>= 1) {
        if (t < o) sm[t] = fmaxf(sm[t], sm[t + o]);
        __syncthreads();
    }
    float mx = sm[0];
    __syncthreads();
    float ex = 0.f;
    if (t < 256) { ex = expf(x - mx); sm[t] = ex; }
    __syncthreads();
    for (int o = 128; o > 0; o >>= 1) {
        if (t < o) sm[t] += sm[t + o];
        __syncthreads();
    }
    float Z = sm[0];
    __syncthreads();
    if (t < 256) c[t] = ex / Z;
    __syncthreads();
    float acc = 0.f;
    const float* eb = enc + (size_t)b * SS * HH + t;
#pragma unroll 4
    for (int s = 0; s < SS; s++) acc += c[s] * eb[s * HH];
    y[b * (2 * HH) + HH + t] = acc;
}

// finish Z with score_c exps; probc = ec/Z; invz; pcsum += rowsum(probc)
__global__ __launch_bounds__(256)
void probc_z_kernel(const float* __restrict__ c, const int* __restrict__ eidx,
                    float* __restrict__ zrow, float* __restrict__ invz,
                    float* __restrict__ pc, float* __restrict__ pcsum)
{
    int b = blockIdx.x, t = threadIdx.x;
    int e = eidx[b * SS + t];
    float x = c[b * SS + t] + ((e == 0) ? -1000.f : 0.f);
    float ec = __expf(x);
    __shared__ float sm[256];
    __shared__ float iZs;
    sm[t] = ec; __syncthreads();
    for (int o = 128; o > 0; o >>= 1) { if (t < o) sm[t] += sm[t + o]; __syncthreads(); }
    if (t == 0) {
        float Z = zrow[b] + sm[0];
        float iZ = 1.f / Z;
        iZs = iZ;
        invz[b] = iZ;
        atomicAdd(pcsum, sm[0] * iZ);
    }
    __syncthreads();
    pc[b * SS + t] = ec * iZs;
}

// prob_g_ext write: out = E * invZ
#define NWG ((BB * VEXT) / 256)   // 25006, exact
__global__ __launch_bounds__(256)
void finalize_kernel(const float* __restrict__ E, const float* __restrict__ invz,
                     float* __restrict__ out)
{
    int i = blockIdx.x * 256 + threadIdx.x;
    int b = i / VEXT;
    int j = i - b * VEXT;
    out[i] = (j < VV) ? E[(size_t)b * VV + j] * invz[b] : 1e-4f;
}

// scatter prob_c into out (first BB blocks) + weighted_new (last BB blocks)
__global__ __launch_bounds__(512)
void scatter_weighted(const int* __restrict__ eidx, const int* __restrict__ iidx,
                      const float* __restrict__ pc, const float* __restrict__ enc,
                      const float* __restrict__ pcsum,
                      float* __restrict__ out, float* __restrict__ outw)
{
    if (blockIdx.x < BB) {
        int b = blockIdx.x, t = threadIdx.x;
        if (t < 256)
            atomicAdd(&out[b * VEXT + eidx[b * SS + t]], pc[b * SS + t]);
        return;
    }
    int b = blockIdx.x - BB, t = threadIdx.x;
    __shared__ float coef[256];
    __shared__ int cnt;
    if (t == 0) cnt = 0;
    __syncthreads();
    if (t < 256) {
        int match = (eidx[b * SS + t] == iidx[b]);
        coef[t] = match ? pc[b * SS + t] : 0.f;
        if (match) atomicAdd(&cnt, 1);
    }
    __syncthreads();
    float scale = 1.f / (*pcsum);
    if (cnt > 1) scale /= (float)cnt;
    float acc = 0.f;
    const float* eb = enc + (size_t)b * SS * HH + t;
#pragma unroll 4
    for (int s = 0; s < SS; s++) acc += coef[s] * eb[s * HH];
    outw[b * HH + t] = acc * scale;
}

// =========================== launch (single stream) ===========================
extern "C" void kernel_launch(void* const* d_in, const int* in_sizes, int n_in,
                              void* d_out, int out_size)
{
    const int*   input_idx   = (const int*)  d_in[0];
    const float* encoded     = (const float*)d_in[1];
    const int*   encoded_idx = (const int*)  d_in[2];
    const float* prev_state  = (const float*)d_in[3];
    const float* embed_table = (const float*)d_in[5];
    const float* Ws_w        = (const float*)d_in[6];
    const float* Ws_b        = (const float*)d_in[7];
    const float* gru_Wih     = (const float*)d_in[8];
    const float* gru_Whh     = (const float*)d_in[9];
    const float* gru_bih     = (const float*)d_in[10];
    const float* gru_bhh     = (const float*)d_in[11];
    const float* attn_W      = (const float*)d_in[12];
    const float* attn_b      = (const float*)d_in[13];
    const float* attn_v      = (const float*)d_in[14];
    const float* Wo_w        = (const float*)d_in[15];
    const float* Wo_b        = (const float*)d_in[16];
    const float* Wc_w        = (const float*)d_in[17];
    const float* Wc_b        = (const float*)d_in[18];

    float* out          = (float*)d_out;
    float* out_state    = out + (size_t)BB * VEXT;
    float* out_weighted = out_state + BB * HH;

    float* sc = nullptr;
    cudaGetSymbolAddress((void**)&sc, g_scratch);
    float* prev   = sc + OFF_PREV;
    float* gi     = sc + OFF_GI;
    float* gh     = sc + OFF_GH;
    float* satt   = sc + OFF_SATT;
    float* state  = sc + OFF_STATE;
    float* energy = sc + OFF_ENERGY;
    float* yv     = sc + OFF_Y;
    float* scoreg = sc + OFF_SCOREG;
    float* scorec = sc + OFF_SCOREC;
    float* probc  = sc + OFF_PROBC;
    float* invz   = sc + OFF_INVZ;
    float* zrow   = sc + OFF_Z;
    float* pcsum  = sc + OFF_PCSUM;

    cudaFuncSetAttribute(hmma_energy, cudaFuncAttributeMaxDynamicSharedMemorySize,
                         V4_DYN);
    cudaFuncSetAttribute(hmma_scores, cudaFuncAttributeMaxDynamicSharedMemorySize,
                         V4_DYN);

    // 1. all zeroing in one launch (invz, zrow, pcsum contiguous)
    zero_all<<<(NZ + 255) / 256, 256>>>(prev, energy, scorec, invz);
    // 2. prev + gi merged (gather fused into gi A-load)
    gemm_chain1<<<64 + 192, 256>>>(prev_state, Ws_w, Ws_b, prev,
                                   input_idx, embed_table, gru_Wih, gru_bih, gi);
    // 3. gh
    gemm128_splitk<<<dim3(3 * HH / 64, 8), 256>>>(prev, HH, gru_Whh, HH,
                                                  gru_bhh, gh, 3 * HH, HH);
    // 4. GRU
    gru_kernel<<<(BB * HH) / 256, 256>>>(gi, gh, prev, state, yv, out_state);
    // 5. satt
    gemm128_splitk<<<dim3(HH / 64, 8), 256>>>(state, HH, attn_W, 2 * HH,
                                              attn_b, satt, HH, HH);
    // 6. energy GEMM (M-tile 64 -> 1024 blocks, ~7 waves)
    hmma_energy<<<dim3(512, 2), 256, V4_DYN>>>(encoded, attn_W, satt, attn_v,
                                               energy);
    // 7. attention softmax + context
    softmax_context<<<BB, 512>>>(energy, encoded, yv);
    // 8. merged score_g (exp epilogue -> E + zrow) + score_c
    hmma_scores<<<NT_G + NT_C, 256, V4_DYN>>>(
        yv, Wo_w, Wo_b, encoded, Wc_w, Wc_b, scoreg, zrow, scorec);
    // 9. finish Z with score_c; probc; invz; pcsum
    probc_z_kernel<<<BB, SS>>>(scorec, encoded_idx, zrow, invz, probc, pcsum);
    // 10. prob_g_ext write (pure multiply)
    finalize_kernel<<<NWG, 256>>>(scoreg, invz, out);
    // 11. scatter + weighted_new merged
    scatter_weighted<<<2 * BB, 512>>>(encoded_idx, input_idx, probc, encoded,
                                      pcsum, out, out_weighted);
}

// round 14
// speedup vs baseline: 1.0487x; 1.0487x over previous
#include <cuda_runtime.h>
#include <cuda_fp16.h>
#include <math.h>
#include <stdint.h>

#define VV 50000
#define EE 512
#define HH 512
#define BB 128
#define SS 256
#define OOV 12
#define VEXT (VV + OOV)   // 50012

// ---------------- fp32 scratch ----------------
#define OFF_PREV   0
#define OFF_GI     (OFF_PREV + BB*HH)
#define OFF_GH     (OFF_GI + BB*3*HH)
#define OFF_SATT   (OFF_GH + BB*3*HH)
#define NZEND      (OFF_SATT + BB*HH)
#define NZ         NZEND
#define OFF_STATE  NZEND
#define OFF_ENERGY (OFF_STATE + BB*HH)
#define OFF_Y      (OFF_ENERGY + BB*SS)
#define OFF_SCOREG (OFF_Y + BB*2*HH)
#define OFF_SCOREC (OFF_SCOREG + (size_t)BB*VV)
#define OFF_PROBC  (OFF_SCOREC + BB*SS)
#define OFF_INVZ   (OFF_PROBC + BB*SS)
#define OFF_Z      (OFF_INVZ + BB)
#define OFF_PCSUM  (OFF_Z + BB)
#define SCRATCH_FLOATS (OFF_PCSUM + 64)

__device__ float g_scratch[SCRATCH_FLOATS];

// ---------------- helpers ----------------
__device__ __forceinline__ uint32_t smem_u32(const void* p) {
    uint32_t a;
    asm("{ .reg .u64 t; cvta.to.shared.u64 t, %1; cvt.u32.u64 %0, t; }"
        : "=r"(a) : "l"(p));
    return a;
}
static __device__ __forceinline__ uint32_t SWZ(uint32_t o) {
    return o ^ ((o >> 3) & 0x70u);
}
__device__ __forceinline__ void cpa16(uint32_t dst, const void* src, int srcsize) {
    asm volatile("cp.async.cg.shared.global [%0], [%1], 16, %2;"
                 :: "r"(dst), "l"(src), "r"(srcsize) : "memory");
}
__device__ __forceinline__ void cpa_commit() {
    asm volatile("cp.async.commit_group;" ::: "memory");
}
__device__ __forceinline__ void cpa_wait0() {
    asm volatile("cp.async.wait_group 0;" ::: "memory");
}
__device__ __forceinline__ void ldm_x4(uint32_t& r0, uint32_t& r1,
                                       uint32_t& r2, uint32_t& r3, uint32_t a) {
    asm volatile("ldmatrix.sync.aligned.m8n8.x4.shared.b16 {%0,%1,%2,%3}, [%4];"
                 : "=r"(r0), "=r"(r1), "=r"(r2), "=r"(r3) : "r"(a));
}
__device__ __forceinline__ void mma16816(float& c0, float& c1, float& c2, float& c3,
                                         uint32_t a0, uint32_t a1, uint32_t a2,
                                         uint32_t a3, uint32_t b0, uint32_t b1) {
    asm volatile("mma.sync.aligned.m16n8k16.row.col.f32.f16.f16.f32 "
                 "{%0,%1,%2,%3}, {%4,%5,%6,%7}, {%8,%9}, {%0,%1,%2,%3};"
                 : "+f"(c0), "+f"(c1), "+f"(c2), "+f"(c3)
                 : "r"(a0), "r"(a1), "r"(a2), "r"(a3), "r"(b0), "r"(b1));
}
// fast tanh: 1 - 2/(exp(2x)+1); abs err ~1e-7
__device__ __forceinline__ float fast_tanh(float x) {
    float e = __expf(2.f * x);
    return 1.f - __fdividef(2.f, e + 1.f);
}

// ============ HMMA core: fp32 in, 3-term split, convert/MMA overlapped ======
// Block tile 128 x 256 (MI=4, NJ=8). k-chunk = 32 fp32 cols.
// mode 0: outS = D + add_s[n]
// mode 1: atomicAdd(outv[row0+m], sum_n fast_tanh(D + add_s[n]) * wv_s[n])
// mode 2: outS = __expf(D + add_s[n]); atomicAdd(outv[row0+m], row-sum)
#define V4_SA(p)  ((p) * 16384)
#define V4_SB(p)  (32768 + (p) * 32768)
#define V4_HA(p)  (98304 + (p) * 16384)
#define V4_HB(p)  (131072 + (p) * 32768)
#define V4_ADD    196608
#define V4_WV     197632
#define V4_DYN    (198656 + 1024)

__device__ __forceinline__ void hmma_core8(
    char* smem,
    const float* __restrict__ A, int lda, int K,
    const float* __restrict__ B, int ldb, int bcol, int Nrows,
    int mode,
    const float* __restrict__ addg, int add_per_b, int Ntot,
    const float* __restrict__ wvg, int wv_per_b,
    float* __restrict__ outS, int ldout,
    float* __restrict__ outv,
    int row0, int n0)
{
    constexpr int NJ = 8;
    const uint32_t sb = smem_u32(smem);
    const int tid = threadIdx.x, wid = tid >> 5, lid = tid & 31;
    const int b    = row0 >> 8;
    const int wm0  = (wid >> 2) * 64;
    const int wn0  = (wid & 3) * (NJ * 8);
    constexpr int TOT = 4 + NJ;

    float* add_s = (float*)(smem + V4_ADD);
    float* wv_s  = (float*)(smem + V4_WV);
    {
        int gn = n0 + tid;
        if (mode != 1) {
            add_s[tid] = (gn < Nrows) ? addg[gn] : 0.f;
        } else {
            add_s[tid] = add_per_b ? addg[(size_t)b * Ntot + gn] : addg[gn];
            wv_s[tid]  = wv_per_b ? wvg[(size_t)b * Ntot + gn] : wvg[gn];
        }
    }

    const int nc = K >> 5;

    auto issue = [&](int c, int par) {
        int k0 = c << 5;
#pragma unroll
        for (int i = 0; i < 4; i++) {
            int u = tid + i * 256;
            int r = u >> 3, b16 = u & 7;
            cpa16(sb + V4_SA(par) + (uint32_t)(r * 128 + b16 * 16),
                  &A[(size_t)(row0 + r) * lda + k0 + b16 * 4], 16);
        }
#pragma unroll
        for (int i = 0; i < NJ; i++) {
            int u = tid + i * 256;
            int r = u >> 3, b16 = u & 7;
            int gr = n0 + r;
            int ok = (gr < Nrows) ? 16 : 0;
            int grc = (gr < Nrows) ? gr : 0;
            cpa16(sb + V4_SB(par) + (uint32_t)(r * 128 + b16 * 16),
                  &B[(size_t)grc * ldb + bcol + k0 + b16 * 4], ok);
        }
        cpa_commit();
    };

    auto conv_range = [&](int par, int i0, int i1) {
        for (int i = i0; i < i1; i++) {
            int stage_off, h_off, idx;
            if (i < 4) { idx = tid + i * 256; stage_off = V4_SA(par); h_off = V4_HA(par); }
            else       { idx = tid + (i - 4) * 256; stage_off = V4_SB(par); h_off = V4_HB(par); }
            int r = idx >> 3, c4 = idx & 7;
            float4 v = *(const float4*)(smem + stage_off + r * 128 + c4 * 16);
            __half2 h01 = __float22half2_rn(make_float2(v.x, v.y));
            __half2 h23 = __float22half2_rn(make_float2(v.z, v.w));
            float2 f01 = __half22float2(h01);
            float2 f23 = __half22float2(h23);
            __half2 l01 = __float22half2_rn(make_float2(v.x - f01.x, v.y - f01.y));
            __half2 l23 = __float22half2_rn(make_float2(v.z - f23.x, v.w - f23.y));
            uint2 hv = make_uint2(*(uint32_t*)&h01, *(uint32_t*)&h23);
            uint2 lv = make_uint2(*(uint32_t*)&l01, *(uint32_t*)&l23);
            *(uint2*)(smem + h_off + SWZ((uint32_t)(r * 128 + c4 * 8))) = hv;
            *(uint2*)(smem + h_off + SWZ((uint32_t)(r * 128 + 64 + c4 * 8))) = lv;
        }
    };

    float cacc[4][NJ][4];
#pragma unroll
    for (int mi = 0; mi < 4; mi++)
#pragma unroll
        for (int nj = 0; nj < NJ; nj++)
#pragma unroll
            for (int f = 0; f < 4; f++) cacc[mi][nj][f] = 0.f;

    const int a_row  = wm0 + (lid & 15);
    const int a_csel = ((lid >> 4) & 1) * 16;
    const int b_rowo = (lid & 7) + ((lid >> 4) & 1) * 8;
    const int b_csel = ((lid >> 3) & 1) * 16;

    issue(0, 0);
    cpa_wait0();
    conv_range(0, 0, TOT);
    if (nc > 1) issue(1, 1);
    __syncthreads();

    for (int c = 0; c < nc; c++) {
        const int par = c & 1;
        const bool more = (c + 1 < nc);
        if (more) {
            cpa_wait0();
            if (c + 2 < nc) issue(c + 2, par);
        }
        const uint32_t ha = sb + V4_HA(par);
        const uint32_t hb = sb + V4_HB(par);
#pragma unroll
        for (int sg = 0; sg < 6; sg++) {
            const int t = sg >> 1, k16 = sg & 1;
            const int aoff = (t == 1) ? 64 : 0;
            const int boff = (t == 2) ? 64 : 0;
            uint32_t a[4][4];
#pragma unroll
            for (int mi = 0; mi < 4; mi++) {
                uint32_t addr = ha + SWZ((uint32_t)((a_row + mi * 16) * 128 +
                                                    aoff + k16 * 32 + a_csel));
                ldm_x4(a[mi][0], a[mi][1], a[mi][2], a[mi][3], addr);
            }
            uint32_t bf[NJ][2];
#pragma unroll
            for (int nj2 = 0; nj2 < NJ / 2; nj2++) {
                uint32_t addr = hb + SWZ((uint32_t)((wn0 + nj2 * 16 + b_rowo) * 128 +
                                                    boff + k16 * 32 + b_csel));
                ldm_x4(bf[2 * nj2][0], bf[2 * nj2][1],
                       bf[2 * nj2 + 1][0], bf[2 * nj2 + 1][1], addr);
            }
            if (more) conv_range(par ^ 1, (TOT * sg) / 6, (TOT * (sg + 1)) / 6);
#pragma unroll
            for (int mi = 0; mi < 4; mi++)
#pragma unroll
                for (int nj = 0; nj < NJ; nj++)
                    mma16816(cacc[mi][nj][0], cacc[mi][nj][1],
                             cacc[mi][nj][2], cacc[mi][nj][3],
                             a[mi][0], a[mi][1], a[mi][2], a[mi][3],
                             bf[nj][0], bf[nj][1]);
        }
        if (more) __syncthreads();
    }

    const int rA = wm0 + (lid >> 2);
    const int lcol = wn0 + 2 * (lid & 3);
    if (mode == 0) {
#pragma unroll
        for (int mi = 0; mi < 4; mi++) {
#pragma unroll
            for (int nj = 0; nj < NJ; nj++) {
                int lc = lcol + nj * 8;
                int n = n0 + lc;
                if (n < Nrows) {
                    int r0r = row0 + rA + mi * 16;
                    float2 v0 = make_float2(cacc[mi][nj][0] + add_s[lc],
                                            cacc[mi][nj][1] + add_s[lc + 1]);
                    float2 v1 = make_float2(cacc[mi][nj][2] + add_s[lc],
                                            cacc[mi][nj][3] + add_s[lc + 1]);
                    *(float2*)&outS[(size_t)r0r * ldout + n] = v0;
                    *(float2*)&outS[(size_t)(r0r + 8) * ldout + n] = v1;
                }
            }
        }
    } else if (mode == 2) {
        // exp + store + per-row sums (no-shift softmax)
#pragma unroll
        for (int mi = 0; mi < 4; mi++) {
            float s0 = 0.f, s1 = 0.f;
#pragma unroll
            for (int nj = 0; nj < NJ; nj++) {
                int lc = lcol + nj * 8;
                int n = n0 + lc;
                if (n < Nrows) {
                    float e0 = __expf(cacc[mi][nj][0] + add_s[lc]);
                    float e1 = __expf(cacc[mi][nj][1] + add_s[lc + 1]);
                    float e2 = __expf(cacc[mi][nj][2] + add_s[lc]);
                    float e3 = __expf(cacc[mi][nj][3] + add_s[lc + 1]);
                    int r0r = row0 + rA + mi * 16;
                    *(float2*)&outS[(size_t)r0r * ldout + n] = make_float2(e0, e1);
                    *(float2*)&outS[(size_t)(r0r + 8) * ldout + n] = make_float2(e2, e3);
                    s0 += e0 + e1;
                    s1 += e2 + e3;
                }
            }
            s0 += __shfl_xor_sync(0xffffffffu, s0, 1);
            s0 += __shfl_xor_sync(0xffffffffu, s0, 2);
            s1 += __shfl_xor_sync(0xffffffffu, s1, 1);
            s1 += __shfl_xor_sync(0xffffffffu, s1, 2);
            if ((lid & 3) == 0) {
                atomicAdd(&outv[row0 + rA + mi * 16], s0);
                atomicAdd(&outv[row0 + rA + mi * 16 + 8], s1);
            }
        }
    } else {
#pragma unroll
        for (int mi = 0; mi < 4; mi++) {
            float p0 = 0.f, p1 = 0.f;
#pragma unroll
            for (int nj = 0; nj < NJ; nj++) {
                int lc = lcol + nj * 8;
                float ad0 = add_s[lc], ad1 = add_s[lc + 1];
                float w0 = wv_s[lc],  w1 = wv_s[lc + 1];
                p0 += fast_tanh(cacc[mi][nj][0] + ad0) * w0
                    + fast_tanh(cacc[mi][nj][1] + ad1) * w1;
                p1 += fast_tanh(cacc[mi][nj][2] + ad0) * w0
                    + fast_tanh(cacc[mi][nj][3] + ad1) * w1;
            }
            p0 += __shfl_xor_sync(0xffffffffu, p0, 1);
            p0 += __shfl_xor_sync(0xffffffffu, p0, 2);
            p1 += __shfl_xor_sync(0xffffffffu, p1, 1);
            p1 += __shfl_xor_sync(0xffffffffu, p1, 2);
            if ((lid & 3) == 0) {
                atomicAdd(&outv[row0 + rA + mi * 16], p0);
                atomicAdd(&outv[row0 + rA + mi * 16 + 8], p1);
            }
        }
    }
}

// ---- energy GEMM (128-row tiles, grid (256,2)) ----
__global__ __launch_bounds__(256)
void hmma_gemm8(const float* __restrict__ A, int lda, int K,
                const float* __restrict__ B, int ldb, int bcol, int Nrows,
                int mode,
                const float* __restrict__ addg, int add_per_b, int Ntot,
                const float* __restrict__ wvg, int wv_per_b,
                float* __restrict__ outS, int ldout,
                float* __restrict__ outv)
{
    extern __shared__ char smem_raw[];
    char* smem = (char*)(((uintptr_t)smem_raw + 1023) & ~(uintptr_t)1023);
    hmma_core8(smem, A, lda, K, B, ldb, bcol, Nrows, mode,
               addg, add_per_b, Ntot, wvg, wv_per_b, outS, ldout, outv,
               blockIdx.x * 128, blockIdx.y * 256);
}

// ---- merged score_g(exp) + score_c GEMM ----
#define NT_G 196
#define NT_C 1024
__global__ __launch_bounds__(256)
void hmma_scores(const float* __restrict__ yv,
                 const float* __restrict__ Wo, const float* __restrict__ Wob,
                 const float* __restrict__ enc,
                 const float* __restrict__ Wc, const float* __restrict__ Wcb,
                 float* __restrict__ scoregE, float* __restrict__ zrow,
                 float* __restrict__ scorec)
{
    extern __shared__ char smem_raw[];
    char* smem = (char*)(((uintptr_t)smem_raw + 1023) & ~(uintptr_t)1023);
    int tile = blockIdx.x;
    if (tile < NT_G) {
        hmma_core8(smem, yv, 1024, 1024, Wo, 1024, 0, VV, 2,
                   Wob, 0, 0, nullptr, 0, scoregE, VV, zrow,
                   0, tile * 256);
    } else {
        int t2 = tile - NT_G;
        hmma_core8(smem, enc, 512, 512, Wc, 512, 0, 1024, 1,
                   Wcb, 0, 1024, yv, 1, nullptr, 0, scorec,
                   (t2 >> 2) * 128, (t2 & 3) * 256);
    }
}

// ================= FFMA2 small GEMM =================
__device__ __forceinline__ void ffma2(unsigned long long &c,
                                      unsigned long long a,
                                      unsigned long long b) {
    asm("fma.rn.f32x2 %0, %1, %2, %0;" : "+l"(c) : "l"(a), "l"(b));
}
struct __align__(16) ull2 { unsigned long long x, y; };
__device__ __forceinline__ float f2lo(unsigned long long v) {
    return __uint_as_float((unsigned int)v);
}
__device__ __forceinline__ float f2hi(unsigned long long v) {
    return __uint_as_float((unsigned int)(v >> 32));
}
__device__ __forceinline__ unsigned long long dupf(float v) {
    unsigned int u = __float_as_uint(v);
    unsigned long long r;
    asm("mov.b64 %0, {%1, %1};" : "=l"(r) : "r"(u));
    return r;
}
#define K16_FFMA2_LOOP(acc, Asm, Wsm, ty, tx)                                 \
    _Pragma("unroll")                                                         \
    for (int kk = 0; kk < 16; kk++) {                                         \
        ull2 a01 = *(const ull2*)&Asm[kk][(ty) * 8];                          \
        ull2 a23 = *(const ull2*)&Asm[kk][(ty) * 8 + 4];                      \
        float4 wq = *(const float4*)&Wsm[kk][(tx) * 4];                       \
        unsigned long long w0 = dupf(wq.x), w1 = dupf(wq.y);                  \
        unsigned long long w2 = dupf(wq.z), w3 = dupf(wq.w);                  \
        ffma2(acc[0][0], a01.x, w0); ffma2(acc[0][1], a01.x, w1);             \
        ffma2(acc[0][2], a01.x, w2); ffma2(acc[0][3], a01.x, w3);             \
        ffma2(acc[1][0], a01.y, w0); ffma2(acc[1][1], a01.y, w1);             \
        ffma2(acc[1][2], a01.y, w2); ffma2(acc[1][3], a01.y, w3);             \
        ffma2(acc[2][0], a23.x, w0); ffma2(acc[2][1], a23.x, w1);             \
        ffma2(acc[2][2], a23.x, w2); ffma2(acc[2][3], a23.x, w3);             \
        ffma2(acc[3][0], a23.y, w0); ffma2(acc[3][1], a23.y, w1);             \
        ffma2(acc[3][2], a23.y, w2); ffma2(acc[3][3], a23.y, w3);             \
    }

__device__ __forceinline__ void gemm128_core(
    const float* __restrict__ A, int lda, const int* __restrict__ aidx,
    const float* __restrict__ W, int ldw, const float* __restrict__ bias,
    float* __restrict__ C, int N, int n0, int ks, int kl, bool addbias)
{
    __shared__ float Asm[16][132];
    __shared__ float Wsm[16][68];
    const int tid = threadIdx.x;
    const int ty = tid >> 4, tx = tid & 15;
    const int am  = tid >> 2;
    const int akv = (tid & 3) << 2;

    unsigned long long acc[4][4];
#pragma unroll
    for (int i = 0; i < 4; i++)
#pragma unroll
        for (int j = 0; j < 4; j++) acc[i][j] = 0ull;

    for (int k0 = ks; k0 < ks + kl; k0 += 16) {
        __syncthreads();
#pragma unroll
        for (int r = 0; r < 2; r++) {
            int m = am + r * 64;
            long arow = aidx ? (long)aidx[m] : (long)m;
            float4 v = *(const float4*)&A[arow * lda + k0 + akv];
            Asm[akv+0][m] = v.x; Asm[akv+1][m] = v.y;
            Asm[akv+2][m] = v.z; Asm[akv+3][m] = v.w;
        }
        {
            float4 v = *(const float4*)&W[(size_t)(n0 + am) * ldw + k0 + akv];
            Wsm[akv+0][am] = v.x; Wsm[akv+1][am] = v.y;
            Wsm[akv+2][am] = v.z; Wsm[akv+3][am] = v.w;
        }
        __syncthreads();
        K16_FFMA2_LOOP(acc, Asm, Wsm, ty, tx)
    }
#pragma unroll
    for (int r2 = 0; r2 < 4; r2++) {
#pragma unroll
        for (int j = 0; j < 4; j++) {
            int n = n0 + tx * 4 + j;
            float bsum = (addbias && bias) ? bias[n] : 0.f;
            int m0 = ty * 8 + 2 * r2;
            atomicAdd(&C[(size_t)m0 * N + n],       f2lo(acc[r2][j]) + bsum);
            atomicAdd(&C[(size_t)(m0 + 1) * N + n], f2hi(acc[r2][j]) + bsum);
        }
    }
}

__global__ __launch_bounds__(256)
void gemm128_splitk(const float* __restrict__ A, int lda,
                    const float* __restrict__ W, int ldw,
                    const float* __restrict__ bias,
                    float* __restrict__ C, int N, int Ktot)
{
    int kl = Ktot / gridDim.y;
    gemm128_core(A, lda, nullptr, W, ldw, bias, C, N,
                 blockIdx.x * 64, blockIdx.y * kl, kl, blockIdx.y == 0);
}

// merged: prev = prev_state@Ws^T + Ws_b  AND  gi = embed[idx]@Wih[:, :E]^T + bih
__global__ __launch_bounds__(256)
void gemm_chain1(const float* __restrict__ prev_state,
                 const float* __restrict__ Ws_w, const float* __restrict__ Ws_b,
                 float* __restrict__ prev,
                 const int* __restrict__ input_idx,
                 const float* __restrict__ embed_table,
                 const float* __restrict__ gru_Wih,
                 const float* __restrict__ gru_bih,
                 float* __restrict__ gi)
{
    int bx = blockIdx.x;
    if (bx < 64) {
        int n0 = (bx & 7) * 64, kb = bx >> 3;
        gemm128_core(prev_state, HH, nullptr, Ws_w, HH, Ws_b, prev, HH,
                     n0, kb * 64, 64, kb == 0);
    } else {
        bx -= 64;
        int n0 = (bx % 24) * 64, kb = bx / 24;
        gemm128_core(embed_table, EE, input_idx, gru_Wih, EE + HH, gru_bih,
                     gi, 3 * HH, n0, kb * 64, 64, kb == 0);
    }
}

// zero split-K accumulators + energy + scorec + zrow/invz/pcsum (one launch)
__global__ __launch_bounds__(256)
void zero_all(float* __restrict__ base, float* __restrict__ energy,
              float* __restrict__ scorec, float* __restrict__ tailz)
{
    int i = blockIdx.x * 256 + threadIdx.x;
    if (i < NZ) base[i] = 0.f;
    if (i < BB * SS) { energy[i] = 0.f; scorec[i] = 0.f; }
    if (i < 2 * BB + 1) tailz[i] = 0.f;   // invz, zrow, pcsum
}

__global__ __launch_bounds__(256)
void gru_kernel(const float* __restrict__ gi, const float* __restrict__ gh,
                const float* __restrict__ prev,
                float* __restrict__ state, float* __restrict__ y,
                float* __restrict__ out_state)
{
    int i = blockIdx.x * 256 + threadIdx.x;
    int b = i / HH, h = i - b * HH;
    const float* gib = gi + b * 3 * HH;
    const float* ghb = gh + b * 3 * HH;
    float i_r = gib[h],          h_r = ghb[h];
    float i_z = gib[HH + h],     h_z = ghb[HH + h];
    float i_n = gib[2 * HH + h], h_n = ghb[2 * HH + h];
    float r = 1.f / (1.f + expf(-(i_r + h_r)));
    float z = 1.f / (1.f + expf(-(i_z + h_z)));
    float n = tanhf(i_n + r * h_n);
    float st = (1.f - z) * n + z * prev[i];
    state[i] = st;
    y[b * (2 * HH) + h] = st;
    out_state[i] = st;
}

// fused attention softmax + context
__global__ __launch_bounds__(512)
void softmax_context(const float* __restrict__ e, const float* __restrict__ enc,
                     float* __restrict__ y)
{
    int b = blockIdx.x, t = threadIdx.x;
    __shared__ float sm[256];
    __shared__ float c[256];
    float x = 0.f;
    if (t < 256) { x = e[b * SS + t]; sm[t] = x; }
    __syncthreads();
    for (int o = 128; o > 0; o >>= 1) {
        if (t < o) sm[t] = fmaxf(sm[t], sm[t + o]);
        __syncthreads();
    }
    float mx = sm[0];
    __syncthreads();
    float ex = 0.f;
    if (t < 256) { ex = expf(x - mx); sm[t] = ex; }
    __syncthreads();
    for (int o = 128; o > 0; o >>= 1) {
        if (t < o) sm[t] += sm[t + o];
        __syncthreads();
    }
    float Z = sm[0];
    __syncthreads();
    if (t < 256) c[t] = ex / Z;
    __syncthreads();
    float acc = 0.f;
    const float* eb = enc + (size_t)b * SS * HH + t;
#pragma unroll 4
    for (int s = 0; s < SS; s++) acc += c[s] * eb[s * HH];
    y[b * (2 * HH) + HH + t] = acc;
}

// finish Z with score_c exps; probc = ec/Z; invz; pcsum += rowsum(probc)
__global__ __launch_bounds__(256)
void probc_z_kernel(const float* __restrict__ c, const int* __restrict__ eidx,
                    float* __restrict__ zrow, float* __restrict__ invz,
                    float* __restrict__ pc, float* __restrict__ pcsum)
{
    int b = blockIdx.x, t = threadIdx.x;
    int e = eidx[b * SS + t];
    float x = c[b * SS + t] + ((e == 0) ? -1000.f : 0.f);
    float ec = __expf(x);
    __shared__ float sm[256];
    __shared__ float iZs;
    sm[t] = ec; __syncthreads();
    for (int o = 128; o > 0; o >>= 1) { if (t < o) sm[t] += sm[t + o]; __syncthreads(); }
    if (t == 0) {
        float Z = zrow[b] + sm[0];
        float iZ = 1.f / Z;
        iZs = iZ;
        invz[b] = iZ;
        atomicAdd(pcsum, sm[0] * iZ);
    }
    __syncthreads();
    pc[b * SS + t] = ec * iZs;
}

// prob_g_ext write: out = E * invZ
#define NWG ((BB * VEXT) / 256)   // 25006, exact
__global__ __launch_bounds__(256)
void finalize_kernel(const float* __restrict__ E, const float* __restrict__ invz,
                     float* __restrict__ out)
{
    int i = blockIdx.x * 256 + threadIdx.x;
    int b = i / VEXT;
    int j = i - b * VEXT;
    out[i] = (j < VV) ? E[(size_t)b * VV + j] * invz[b] : 1e-4f;
}

// scatter prob_c into out (first BB blocks) + weighted_new (last BB blocks)
__global__ __launch_bounds__(512)
void scatter_weighted(const int* __restrict__ eidx, const int* __restrict__ iidx,
                      const float* __restrict__ pc, const float* __restrict__ enc,
                      const float* __restrict__ pcsum,
                      float* __restrict__ out, float* __restrict__ outw)
{
    if (blockIdx.x < BB) {
        int b = blockIdx.x, t = threadIdx.x;
        if (t < 256)
            atomicAdd(&out[b * VEXT + eidx[b * SS + t]], pc[b * SS + t]);
        return;
    }
    int b = blockIdx.x - BB, t = threadIdx.x;
    __shared__ float coef[256];
    __shared__ int cnt;
    if (t == 0) cnt = 0;
    __syncthreads();
    if (t < 256) {
        int match = (eidx[b * SS + t] == iidx[b]);
        coef[t] = match ? pc[b * SS + t] : 0.f;
        if (match) atomicAdd(&cnt, 1);
    }
    __syncthreads();
    float scale = 1.f / (*pcsum);
    if (cnt > 1) scale /= (float)cnt;
    float acc = 0.f;
    const float* eb = enc + (size_t)b * SS * HH + t;
#pragma unroll 4
    for (int s = 0; s < SS; s++) acc += coef[s] * eb[s * HH];
    outw[b * HH + t] = acc * scale;
}

// =========================== launch (single stream) ===========================
extern "C" void kernel_launch(void* const* d_in, const int* in_sizes, int n_in,
                              void* d_out, int out_size)
{
    const int*   input_idx   = (const int*)  d_in[0];
    const float* encoded     = (const float*)d_in[1];
    const int*   encoded_idx = (const int*)  d_in[2];
    const float* prev_state  = (const float*)d_in[3];
    const float* embed_table = (const float*)d_in[5];
    const float* Ws_w        = (const float*)d_in[6];
    const float* Ws_b        = (const float*)d_in[7];
    const float* gru_Wih     = (const float*)d_in[8];
    const float* gru_Whh     = (const float*)d_in[9];
    const float* gru_bih     = (const float*)d_in[10];
    const float* gru_bhh     = (const float*)d_in[11];
    const float* attn_W      = (const float*)d_in[12];
    const float* attn_b      = (const float*)d_in[13];
    const float* attn_v      = (const float*)d_in[14];
    const float* Wo_w        = (const float*)d_in[15];
    const float* Wo_b        = (const float*)d_in[16];
    const float* Wc_w        = (const float*)d_in[17];
    const float* Wc_b        = (const float*)d_in[18];

    float* out          = (float*)d_out;
    float* out_state    = out + (size_t)BB * VEXT;
    float* out_weighted = out_state + BB * HH;

    float* sc = nullptr;
    cudaGetSymbolAddress((void**)&sc, g_scratch);
    float* prev   = sc + OFF_PREV;
    float* gi     = sc + OFF_GI;
    float* gh     = sc + OFF_GH;
    float* satt   = sc + OFF_SATT;
    float* state  = sc + OFF_STATE;
    float* energy = sc + OFF_ENERGY;
    float* yv     = sc + OFF_Y;
    float* scoreg = sc + OFF_SCOREG;
    float* scorec = sc + OFF_SCOREC;
    float* probc  = sc + OFF_PROBC;
    float* invz   = sc + OFF_INVZ;
    float* zrow   = sc + OFF_Z;
    float* pcsum  = sc + OFF_PCSUM;

    cudaFuncSetAttribute(hmma_gemm8, cudaFuncAttributeMaxDynamicSharedMemorySize,
                         V4_DYN);
    cudaFuncSetAttribute(hmma_scores, cudaFuncAttributeMaxDynamicSharedMemorySize,
                         V4_DYN);

    // 1. all zeroing in one launch
    zero_all<<<(NZ + 255) / 256, 256>>>(prev, energy, scorec, invz);
    // 2. prev + gi merged (gather fused into gi A-load)
    gemm_chain1<<<64 + 192, 256>>>(prev_state, Ws_w, Ws_b, prev,
                                   input_idx, embed_table, gru_Wih, gru_bih, gi);
    // 3. gh
    gemm128_splitk<<<dim3(3 * HH / 64, 8), 256>>>(prev, HH, gru_Whh, HH,
                                                  gru_bhh, gh, 3 * HH, HH);
    // 4. GRU
    gru_kernel<<<(BB * HH) / 256, 256>>>(gi, gh, prev, state, yv, out_state);
    // 5. satt
    gemm128_splitk<<<dim3(HH / 64, 8), 256>>>(state, HH, attn_W, 2 * HH,
                                              attn_b, satt, HH, HH);
    // 6. energy GEMM (128-row tiles, 512 blocks)
    hmma_gemm8<<<dim3(256, 2), 256, V4_DYN>>>(
        encoded, 512, 512,
        attn_W, 1024, 512, 512,
        1, satt, 1, 512, attn_v, 0,
        nullptr, 0, energy);
    // 7. attention softmax + context
    softmax_context<<<BB, 512>>>(energy, encoded, yv);
    // 8. merged score_g (exp epilogue -> E + zrow) + score_c
    hmma_scores<<<NT_G + NT_C, 256, V4_DYN>>>(
        yv, Wo_w, Wo_b, encoded, Wc_w, Wc_b, scoreg, zrow, scorec);
    // 9. finish Z with score_c; probc; invz; pcsum
    probc_z_kernel<<<BB, SS>>>(scorec, encoded_idx, zrow, invz, probc, pcsum);
    // 10. prob_g_ext write (pure multiply)
    finalize_kernel<<<NWG, 256>>>(scoreg, invz, out);
    // 11. scatter + weighted_new merged
    scatter_weighted<<<2 * BB, 512>>>(encoded_idx, input_idx, probc, encoded,
                                      pcsum, out, out_weighted);
}

// round 15
// speedup vs baseline: 1.1626x; 1.1086x over previous
#include <cuda_runtime.h>
#include <cuda_fp16.h>
#include <math.h>
#include <stdint.h>

#define VV 50000
#define EE 512
#define HH 512
#define BB 128
#define SS 256
#define OOV 12
#define VEXT (VV + OOV)   // 50012

// ---------------- fp32 scratch ----------------
#define OFF_PREV   0
#define OFF_GI     (OFF_PREV + BB*HH)
#define OFF_GH     (OFF_GI + BB*3*HH)
#define OFF_SATT   (OFF_GH + BB*3*HH)
#define NZEND      (OFF_SATT + BB*HH)
#define NZ         NZEND
#define OFF_STATE  NZEND
#define OFF_ENERGY (OFF_STATE + BB*HH)
#define OFF_Y      (OFF_ENERGY + BB*SS)
#define OFF_SCOREG (OFF_Y + BB*2*HH)
#define OFF_SCOREC (OFF_SCOREG + (size_t)BB*VV)
#define OFF_PROBC  (OFF_SCOREC + BB*SS)
#define OFF_INVZ   (OFF_PROBC + BB*SS)
#define OFF_Z      (OFF_INVZ + BB)
#define OFF_PCSUM  (OFF_Z + BB)
#define SCRATCH_FLOATS (OFF_PCSUM + 64)

__device__ float g_scratch[SCRATCH_FLOATS];

// ---------------- helpers ----------------
__device__ __forceinline__ uint32_t smem_u32(const void* p) {
    uint32_t a;
    asm("{ .reg .u64 t; cvta.to.shared.u64 t, %1; cvt.u32.u64 %0, t; }"
        : "=r"(a) : "l"(p));
    return a;
}
static __device__ __forceinline__ uint32_t SWZ(uint32_t o) {
    return o ^ ((o >> 3) & 0x70u);
}
__device__ __forceinline__ void cpa16(uint32_t dst, const void* src, int srcsize) {
    asm volatile("cp.async.cg.shared.global [%0], [%1], 16, %2;"
                 :: "r"(dst), "l"(src), "r"(srcsize) : "memory");
}
__device__ __forceinline__ void cpa_commit() {
    asm volatile("cp.async.commit_group;" ::: "memory");
}
__device__ __forceinline__ void cpa_wait0() {
    asm volatile("cp.async.wait_group 0;" ::: "memory");
}
__device__ __forceinline__ void ldm_x4(uint32_t& r0, uint32_t& r1,
                                       uint32_t& r2, uint32_t& r3, uint32_t a) {
    asm volatile("ldmatrix.sync.aligned.m8n8.x4.shared.b16 {%0,%1,%2,%3}, [%4];"
                 : "=r"(r0), "=r"(r1), "=r"(r2), "=r"(r3) : "r"(a));
}
__device__ __forceinline__ void mma16816(float& c0, float& c1, float& c2, float& c3,
                                         uint32_t a0, uint32_t a1, uint32_t a2,
                                         uint32_t a3, uint32_t b0, uint32_t b1) {
    asm volatile("mma.sync.aligned.m16n8k16.row.col.f32.f16.f16.f32 "
                 "{%0,%1,%2,%3}, {%4,%5,%6,%7}, {%8,%9}, {%0,%1,%2,%3};"
                 : "+f"(c0), "+f"(c1), "+f"(c2), "+f"(c3)
                 : "r"(a0), "r"(a1), "r"(a2), "r"(a3), "r"(b0), "r"(b1));
}
// fast tanh: 1 - 2/(exp(2x)+1); abs err ~1e-7
__device__ __forceinline__ float fast_tanh(float x) {
    float e = __expf(2.f * x);
    return 1.f - __fdividef(2.f, e + 1.f);
}

// ============ HMMA core: fp32 in, NT-term fp16 split, convert/MMA overlap ===
// NT=3: D = Ah.Bh + Al.Bh + Ah.Bl (exact ~2^-22). NT=2: drop Ah.Bl (~2^-12 B rnd).
// Block tile 128 x 256. k-chunk = 32 fp32 cols.
// mode 0: outS = D + add_s[n]
// mode 1: atomicAdd(outv[row0+m], sum_n fast_tanh(D + add_s[n]) * wv_s[n])
// mode 2: outS = __expf(D + add_s[n]); atomicAdd(outv[row0+m], row-sum)
#define V4_SA(p)  ((p) * 16384)
#define V4_SB(p)  (32768 + (p) * 32768)
#define V4_HA(p)  (98304 + (p) * 16384)
#define V4_HB(p)  (131072 + (p) * 32768)
#define V4_ADD    196608
#define V4_WV     197632
#define V4_DYN    (198656 + 1024)

template <int NT>
__device__ __forceinline__ void hmma_core8(
    char* smem,
    const float* __restrict__ A, int lda, int K,
    const float* __restrict__ B, int ldb, int bcol, int Nrows,
    int mode,
    const float* __restrict__ addg, int add_per_b, int Ntot,
    const float* __restrict__ wvg, int wv_per_b,
    float* __restrict__ outS, int ldout,
    float* __restrict__ outv,
    int row0, int n0)
{
    constexpr int NJ = 8;
    const uint32_t sb = smem_u32(smem);
    const int tid = threadIdx.x, wid = tid >> 5, lid = tid & 31;
    const int b    = row0 >> 8;
    const int wm0  = (wid >> 2) * 64;
    const int wn0  = (wid & 3) * (NJ * 8);
    constexpr int TOT = 4 + NJ;

    float* add_s = (float*)(smem + V4_ADD);
    float* wv_s  = (float*)(smem + V4_WV);
    {
        int gn = n0 + tid;
        if (mode != 1) {
            add_s[tid] = (gn < Nrows) ? addg[gn] : 0.f;
        } else {
            add_s[tid] = add_per_b ? addg[(size_t)b * Ntot + gn] : addg[gn];
            wv_s[tid]  = wv_per_b ? wvg[(size_t)b * Ntot + gn] : wvg[gn];
        }
    }

    const int nc = K >> 5;

    auto issue = [&](int c, int par) {
        int k0 = c << 5;
#pragma unroll
        for (int i = 0; i < 4; i++) {
            int u = tid + i * 256;
            int r = u >> 3, b16 = u & 7;
            cpa16(sb + V4_SA(par) + (uint32_t)(r * 128 + b16 * 16),
                  &A[(size_t)(row0 + r) * lda + k0 + b16 * 4], 16);
        }
#pragma unroll
        for (int i = 0; i < NJ; i++) {
            int u = tid + i * 256;
            int r = u >> 3, b16 = u & 7;
            int gr = n0 + r;
            int ok = (gr < Nrows) ? 16 : 0;
            int grc = (gr < Nrows) ? gr : 0;
            cpa16(sb + V4_SB(par) + (uint32_t)(r * 128 + b16 * 16),
                  &B[(size_t)grc * ldb + bcol + k0 + b16 * 4], ok);
        }
        cpa_commit();
    };

    auto conv_range = [&](int par, int i0, int i1) {
        for (int i = i0; i < i1; i++) {
            int stage_off, h_off, idx;
            bool isA = (i < 4);
            if (isA) { idx = tid + i * 256; stage_off = V4_SA(par); h_off = V4_HA(par); }
            else     { idx = tid + (i - 4) * 256; stage_off = V4_SB(par); h_off = V4_HB(par); }
            int r = idx >> 3, c4 = idx & 7;
            float4 v = *(const float4*)(smem + stage_off + r * 128 + c4 * 16);
            __half2 h01 = __float22half2_rn(make_float2(v.x, v.y));
            __half2 h23 = __float22half2_rn(make_float2(v.z, v.w));
            uint2 hv = make_uint2(*(uint32_t*)&h01, *(uint32_t*)&h23);
            *(uint2*)(smem + h_off + SWZ((uint32_t)(r * 128 + c4 * 8))) = hv;
            if (isA || NT == 3) {   // lo needed for A always, for B only if NT=3
                float2 f01 = __half22float2(h01);
                float2 f23 = __half22float2(h23);
                __half2 l01 = __float22half2_rn(make_float2(v.x - f01.x, v.y - f01.y));
                __half2 l23 = __float22half2_rn(make_float2(v.z - f23.x, v.w - f23.y));
                uint2 lv = make_uint2(*(uint32_t*)&l01, *(uint32_t*)&l23);
                *(uint2*)(smem + h_off + SWZ((uint32_t)(r * 128 + 64 + c4 * 8))) = lv;
            }
        }
    };

    float cacc[4][NJ][4];
#pragma unroll
    for (int mi = 0; mi < 4; mi++)
#pragma unroll
        for (int nj = 0; nj < NJ; nj++)
#pragma unroll
            for (int f = 0; f < 4; f++) cacc[mi][nj][f] = 0.f;

    const int a_row  = wm0 + (lid & 15);
    const int a_csel = ((lid >> 4) & 1) * 16;
    const int b_rowo = (lid & 7) + ((lid >> 4) & 1) * 8;
    const int b_csel = ((lid >> 3) & 1) * 16;

    issue(0, 0);
    cpa_wait0();
    conv_range(0, 0, TOT);
    if (nc > 1) issue(1, 1);
    __syncthreads();

    constexpr int NSG = 2 * NT;
    for (int c = 0; c < nc; c++) {
        const int par = c & 1;
        const bool more = (c + 1 < nc);
        if (more) {
            cpa_wait0();
            if (c + 2 < nc) issue(c + 2, par);
        }
        const uint32_t ha = sb + V4_HA(par);
        const uint32_t hb = sb + V4_HB(par);
#pragma unroll
        for (int sg = 0; sg < NSG; sg++) {
            const int t = sg >> 1, k16 = sg & 1;
            const int aoff = (t == 1) ? 64 : 0;
            const int boff = (t == 2) ? 64 : 0;
            uint32_t a[4][4];
#pragma unroll
            for (int mi = 0; mi < 4; mi++) {
                uint32_t addr = ha + SWZ((uint32_t)((a_row + mi * 16) * 128 +
                                                    aoff + k16 * 32 + a_csel));
                ldm_x4(a[mi][0], a[mi][1], a[mi][2], a[mi][3], addr);
            }
            uint32_t bf[NJ][2];
#pragma unroll
            for (int nj2 = 0; nj2 < NJ / 2; nj2++) {
                uint32_t addr = hb + SWZ((uint32_t)((wn0 + nj2 * 16 + b_rowo) * 128 +
                                                    boff + k16 * 32 + b_csel));
                ldm_x4(bf[2 * nj2][0], bf[2 * nj2][1],
                       bf[2 * nj2 + 1][0], bf[2 * nj2 + 1][1], addr);
            }
            if (more) conv_range(par ^ 1, (TOT * sg) / NSG, (TOT * (sg + 1)) / NSG);
#pragma unroll
            for (int mi = 0; mi < 4; mi++)
#pragma unroll
                for (int nj = 0; nj < NJ; nj++)
                    mma16816(cacc[mi][nj][0], cacc[mi][nj][1],
                             cacc[mi][nj][2], cacc[mi][nj][3],
                             a[mi][0], a[mi][1], a[mi][2], a[mi][3],
                             bf[nj][0], bf[nj][1]);
        }
        if (more) __syncthreads();
    }

    const int rA = wm0 + (lid >> 2);
    const int lcol = wn0 + 2 * (lid & 3);
    if (mode == 0) {
#pragma unroll
        for (int mi = 0; mi < 4; mi++) {
#pragma unroll
            for (int nj = 0; nj < NJ; nj++) {
                int lc = lcol + nj * 8;
                int n = n0 + lc;
                if (n < Nrows) {
                    int r0r = row0 + rA + mi * 16;
                    float2 v0 = make_float2(cacc[mi][nj][0] + add_s[lc],
                                            cacc[mi][nj][1] + add_s[lc + 1]);
                    float2 v1 = make_float2(cacc[mi][nj][2] + add_s[lc],
                                            cacc[mi][nj][3] + add_s[lc + 1]);
                    *(float2*)&outS[(size_t)r0r * ldout + n] = v0;
                    *(float2*)&outS[(size_t)(r0r + 8) * ldout + n] = v1;
                }
            }
        }
    } else if (mode == 2) {
#pragma unroll
        for (int mi = 0; mi < 4; mi++) {
            float s0 = 0.f, s1 = 0.f;
#pragma unroll
            for (int nj = 0; nj < NJ; nj++) {
                int lc = lcol + nj * 8;
                int n = n0 + lc;
                if (n < Nrows) {
                    float e0 = __expf(cacc[mi][nj][0] + add_s[lc]);
                    float e1 = __expf(cacc[mi][nj][1] + add_s[lc + 1]);
                    float e2 = __expf(cacc[mi][nj][2] + add_s[lc]);
                    float e3 = __expf(cacc[mi][nj][3] + add_s[lc + 1]);
                    int r0r = row0 + rA + mi * 16;
                    *(float2*)&outS[(size_t)r0r * ldout + n] = make_float2(e0, e1);
                    *(float2*)&outS[(size_t)(r0r + 8) * ldout + n] = make_float2(e2, e3);
                    s0 += e0 + e1;
                    s1 += e2 + e3;
                }
            }
            s0 += __shfl_xor_sync(0xffffffffu, s0, 1);
            s0 += __shfl_xor_sync(0xffffffffu, s0, 2);
            s1 += __shfl_xor_sync(0xffffffffu, s1, 1);
            s1 += __shfl_xor_sync(0xffffffffu, s1, 2);
            if ((lid & 3) == 0) {
                atomicAdd(&outv[row0 + rA + mi * 16], s0);
                atomicAdd(&outv[row0 + rA + mi * 16 + 8], s1);
            }
        }
    } else {
#pragma unroll
        for (int mi = 0; mi < 4; mi++) {
            float p0 = 0.f, p1 = 0.f;
#pragma unroll
            for (int nj = 0; nj < NJ; nj++) {
                int lc = lcol + nj * 8;
                float ad0 = add_s[lc], ad1 = add_s[lc + 1];
                float w0 = wv_s[lc],  w1 = wv_s[lc + 1];
                p0 += fast_tanh(cacc[mi][nj][0] + ad0) * w0
                    + fast_tanh(cacc[mi][nj][1] + ad1) * w1;
                p1 += fast_tanh(cacc[mi][nj][2] + ad0) * w0
                    + fast_tanh(cacc[mi][nj][3] + ad1) * w1;
            }
            p0 += __shfl_xor_sync(0xffffffffu, p0, 1);
            p0 += __shfl_xor_sync(0xffffffffu, p0, 2);
            p1 += __shfl_xor_sync(0xffffffffu, p1, 1);
            p1 += __shfl_xor_sync(0xffffffffu, p1, 2);
            if ((lid & 3) == 0) {
                atomicAdd(&outv[row0 + rA + mi * 16], p0);
                atomicAdd(&outv[row0 + rA + mi * 16 + 8], p1);
            }
        }
    }
}

// ---- energy GEMM: NT=2 (error damped through softmax/context) ----
__global__ __launch_bounds__(256)
void hmma_gemm8(const float* __restrict__ A, int lda, int K,
                const float* __restrict__ B, int ldb, int bcol, int Nrows,
                int mode,
                const float* __restrict__ addg, int add_per_b, int Ntot,
                const float* __restrict__ wvg, int wv_per_b,
                float* __restrict__ outS, int ldout,
                float* __restrict__ outv)
{
    extern __shared__ char smem_raw[];
    char* smem = (char*)(((uintptr_t)smem_raw + 1023) & ~(uintptr_t)1023);
    hmma_core8<2>(smem, A, lda, K, B, ldb, bcol, Nrows, mode,
                  addg, add_per_b, Ntot, wvg, wv_per_b, outS, ldout, outv,
                  blockIdx.x * 128, blockIdx.y * 256);
}

// ---- merged score_g(exp, NT=2) + score_c(NT=3) GEMM ----
#define NT_G 196
#define NT_C 1024
__global__ __launch_bounds__(256)
void hmma_scores(const float* __restrict__ yv,
                 const float* __restrict__ Wo, const float* __restrict__ Wob,
                 const float* __restrict__ enc,
                 const float* __restrict__ Wc, const float* __restrict__ Wcb,
                 float* __restrict__ scoregE, float* __restrict__ zrow,
                 float* __restrict__ scorec)
{
    extern __shared__ char smem_raw[];
    char* smem = (char*)(((uintptr_t)smem_raw + 1023) & ~(uintptr_t)1023);
    int tile = blockIdx.x;
    if (tile < NT_G) {
        hmma_core8<2>(smem, yv, 1024, 1024, Wo, 1024, 0, VV, 2,
                      Wob, 0, 0, nullptr, 0, scoregE, VV, zrow,
                      0, tile * 256);
    } else {
        int t2 = tile - NT_G;
        hmma_core8<3>(smem, enc, 512, 512, Wc, 512, 0, 1024, 1,
                      Wcb, 0, 1024, yv, 1, nullptr, 0, scorec,
                      (t2 >> 2) * 128, (t2 & 3) * 256);
    }
}

// ================= FFMA2 small GEMM =================
__device__ __forceinline__ void ffma2(unsigned long long &c,
                                      unsigned long long a,
                                      unsigned long long b) {
    asm("fma.rn.f32x2 %0, %1, %2, %0;" : "+l"(c) : "l"(a), "l"(b));
}
struct __align__(16) ull2 { unsigned long long x, y; };
__device__ __forceinline__ float f2lo(unsigned long long v) {
    return __uint_as_float((unsigned int)v);
}
__device__ __forceinline__ float f2hi(unsigned long long v) {
    return __uint_as_float((unsigned int)(v >> 32));
}
__device__ __forceinline__ unsigned long long dupf(float v) {
    unsigned int u = __float_as_uint(v);
    unsigned long long r;
    asm("mov.b64 %0, {%1, %1};" : "=l"(r) : "r"(u));
    return r;
}
#define K16_FFMA2_LOOP(acc, Asm, Wsm, ty, tx)                                 \
    _Pragma("unroll")                                                         \
    for (int kk = 0; kk < 16; kk++) {                                         \
        ull2 a01 = *(const ull2*)&Asm[kk][(ty) * 8];                          \
        ull2 a23 = *(const ull2*)&Asm[kk][(ty) * 8 + 4];                      \
        float4 wq = *(const float4*)&Wsm[kk][(tx) * 4];                       \
        unsigned long long w0 = dupf(wq.x), w1 = dupf(wq.y);                  \
        unsigned long long w2 = dupf(wq.z), w3 = dupf(wq.w);                  \
        ffma2(acc[0][0], a01.x, w0); ffma2(acc[0][1], a01.x, w1);             \
        ffma2(acc[0][2], a01.x, w2); ffma2(acc[0][3], a01.x, w3);             \
        ffma2(acc[1][0], a01.y, w0); ffma2(acc[1][1], a01.y, w1);             \
        ffma2(acc[1][2], a01.y, w2); ffma2(acc[1][3], a01.y, w3);             \
        ffma2(acc[2][0], a23.x, w0); ffma2(acc[2][1], a23.x, w1);             \
        ffma2(acc[2][2], a23.x, w2); ffma2(acc[2][3], a23.x, w3);             \
        ffma2(acc[3][0], a23.y, w0); ffma2(acc[3][1], a23.y, w1);             \
        ffma2(acc[3][2], a23.y, w2); ffma2(acc[3][3], a23.y, w3);             \
    }

__device__ __forceinline__ void gemm128_core(
    const float* __restrict__ A, int lda, const int* __restrict__ aidx,
    const float* __restrict__ W, int ldw, const float* __restrict__ bias,
    float* __restrict__ C, int N, int n0, int ks, int kl, bool addbias)
{
    __shared__ float Asm[16][132];
    __shared__ float Wsm[16][68];
    const int tid = threadIdx.x;
    const int ty = tid >> 4, tx = tid & 15;
    const int am  = tid >> 2;
    const int akv = (tid & 3) << 2;

    unsigned long long acc[4][4];
#pragma unroll
    for (int i = 0; i < 4; i++)
#pragma unroll
        for (int j = 0; j < 4; j++) acc[i][j] = 0ull;

    for (int k0 = ks; k0 < ks + kl; k0 += 16) {
        __syncthreads();
#pragma unroll
        for (int r = 0; r < 2; r++) {
            int m = am + r * 64;
            long arow = aidx ? (long)aidx[m] : (long)m;
            float4 v = *(const float4*)&A[arow * lda + k0 + akv];
            Asm[akv+0][m] = v.x; Asm[akv+1][m] = v.y;
            Asm[akv+2][m] = v.z; Asm[akv+3][m] = v.w;
        }
        {
            float4 v = *(const float4*)&W[(size_t)(n0 + am) * ldw + k0 + akv];
            Wsm[akv+0][am] = v.x; Wsm[akv+1][am] = v.y;
            Wsm[akv+2][am] = v.z; Wsm[akv+3][am] = v.w;
        }
        __syncthreads();
        K16_FFMA2_LOOP(acc, Asm, Wsm, ty, tx)
    }
#pragma unroll
    for (int r2 = 0; r2 < 4; r2++) {
#pragma unroll
        for (int j = 0; j < 4; j++) {
            int n = n0 + tx * 4 + j;
            float bsum = (addbias && bias) ? bias[n] : 0.f;
            int m0 = ty * 8 + 2 * r2;
            atomicAdd(&C[(size_t)m0 * N + n],       f2lo(acc[r2][j]) + bsum);
            atomicAdd(&C[(size_t)(m0 + 1) * N + n], f2hi(acc[r2][j]) + bsum);
        }
    }
}

__global__ __launch_bounds__(256)
void gemm128_splitk(const float* __restrict__ A, int lda,
                    const float* __restrict__ W, int ldw,
                    const float* __restrict__ bias,
                    float* __restrict__ C, int N, int Ktot)
{
    int kl = Ktot / gridDim.y;
    gemm128_core(A, lda, nullptr, W, ldw, bias, C, N,
                 blockIdx.x * 64, blockIdx.y * kl, kl, blockIdx.y == 0);
}

// merged: prev = prev_state@Ws^T + Ws_b  AND  gi = embed[idx]@Wih[:, :E]^T + bih
__global__ __launch_bounds__(256)
void gemm_chain1(const float* __restrict__ prev_state,
                 const float* __restrict__ Ws_w, const float* __restrict__ Ws_b,
                 float* __restrict__ prev,
                 const int* __restrict__ input_idx,
                 const float* __restrict__ embed_table,
                 const float* __restrict__ gru_Wih,
                 const float* __restrict__ gru_bih,
                 float* __restrict__ gi)
{
    int bx = blockIdx.x;
    if (bx < 64) {
        int n0 = (bx & 7) * 64, kb = bx >> 3;
        gemm128_core(prev_state, HH, nullptr, Ws_w, HH, Ws_b, prev, HH,
                     n0, kb * 64, 64, kb == 0);
    } else {
        bx -= 64;
        int n0 = (bx % 24) * 64, kb = bx / 24;
        gemm128_core(embed_table, EE, input_idx, gru_Wih, EE + HH, gru_bih,
                     gi, 3 * HH, n0, kb * 64, 64, kb == 0);
    }
}

// zero split-K accumulators + energy + scorec + zrow/invz/pcsum (one launch)
__global__ __launch_bounds__(256)
void zero_all(float* __restrict__ base, float* __restrict__ energy,
              float* __restrict__ scorec, float* __restrict__ tailz)
{
    int i = blockIdx.x * 256 + threadIdx.x;
    if (i < NZ) base[i] = 0.f;
    if (i < BB * SS) { energy[i] = 0.f; scorec[i] = 0.f; }
    if (i < 2 * BB + 1) tailz[i] = 0.f;   // invz, zrow, pcsum
}

__global__ __launch_bounds__(256)
void gru_kernel(const float* __restrict__ gi, const float* __restrict__ gh,
                const float* __restrict__ prev,
                float* __restrict__ state, float* __restrict__ y,
                float* __restrict__ out_state)
{
    int i = blockIdx.x * 256 + threadIdx.x;
    int b = i / HH, h = i - b * HH;
    const float* gib = gi + b * 3 * HH;
    const float* ghb = gh + b * 3 * HH;
    float i_r = gib[h],          h_r = ghb[h];
    float i_z = gib[HH + h],     h_z = ghb[HH + h];
    float i_n = gib[2 * HH + h], h_n = ghb[2 * HH + h];
    float r = 1.f / (1.f + expf(-(i_r + h_r)));
    float z = 1.f / (1.f + expf(-(i_z + h_z)));
    float n = tanhf(i_n + r * h_n);
    float st = (1.f - z) * n + z * prev[i];
    state[i] = st;
    y[b * (2 * HH) + h] = st;
    out_state[i] = st;
}

// fused attention softmax + context
__global__ __launch_bounds__(512)
void softmax_context(const float* __restrict__ e, const float* __restrict__ enc,
                     float* __restrict__ y)
{
    int b = blockIdx.x, t = threadIdx.x;
    __shared__ float sm[256];
    __shared__ float c[256];
    float x = 0.f;
    if (t < 256) { x = e[b * SS + t]; sm[t] = x; }
    __syncthreads();
    for (int o = 128; o > 0; o >>= 1) {
        if (t < o) sm[t] = fmaxf(sm[t], sm[t + o]);
        __syncthreads();
    }
    float mx = sm[0];
    __syncthreads();
    float ex = 0.f;
    if (t < 256) { ex = expf(x - mx); sm[t] = ex; }
    __syncthreads();
    for (int o = 128; o > 0; o >>= 1) {
        if (t < o) sm[t] += sm[t + o];
        __syncthreads();
    }
    float Z = sm[0];
    __syncthreads();
    if (t < 256) c[t] = ex / Z;
    __syncthreads();
    float acc = 0.f;
    const float* eb = enc + (size_t)b * SS * HH + t;
#pragma unroll 4
    for (int s = 0; s < SS; s++) acc += c[s] * eb[s * HH];
    y[b * (2 * HH) + HH + t] = acc;
}

// finish Z with score_c exps; probc = ec/Z; invz; pcsum += rowsum(probc)
__global__ __launch_bounds__(256)
void probc_z_kernel(const float* __restrict__ c, const int* __restrict__ eidx,
                    float* __restrict__ zrow, float* __restrict__ invz,
                    float* __restrict__ pc, float* __restrict__ pcsum)
{
    int b = blockIdx.x, t = threadIdx.x;
    int e = eidx[b * SS + t];
    float x = c[b * SS + t] + ((e == 0) ? -1000.f : 0.f);
    float ec = __expf(x);
    __shared__ float sm[256];
    __shared__ float iZs;
    sm[t] = ec; __syncthreads();
    for (int o = 128; o > 0; o >>= 1) { if (t < o) sm[t] += sm[t + o]; __syncthreads(); }
    if (t == 0) {
        float Z = zrow[b] + sm[0];
        float iZ = 1.f / Z;
        iZs = iZ;
        invz[b] = iZ;
        atomicAdd(pcsum, sm[0] * iZ);
    }
    __syncthreads();
    pc[b * SS + t] = ec * iZs;
}

// prob_g_ext write: out = E * invZ
#define NWG ((BB * VEXT) / 256)   // 25006, exact
__global__ __launch_bounds__(256)
void finalize_kernel(const float* __restrict__ E, const float* __restrict__ invz,
                     float* __restrict__ out)
{
    int i = blockIdx.x * 256 + threadIdx.x;
    int b = i / VEXT;
    int j = i - b * VEXT;
    out[i] = (j < VV) ? E[(size_t)b * VV + j] * invz[b] : 1e-4f;
}

// scatter prob_c into out (first BB blocks) + weighted_new (last BB blocks)
__global__ __launch_bounds__(512)
void scatter_weighted(const int* __restrict__ eidx, const int* __restrict__ iidx,
                      const float* __restrict__ pc, const float* __restrict__ enc,
                      const float* __restrict__ pcsum,
                      float* __restrict__ out, float* __restrict__ outw)
{
    if (blockIdx.x < BB) {
        int b = blockIdx.x, t = threadIdx.x;
        if (t < 256)
            atomicAdd(&out[b * VEXT + eidx[b * SS + t]], pc[b * SS + t]);
        return;
    }
    int b = blockIdx.x - BB, t = threadIdx.x;
    __shared__ float coef[256];
    __shared__ int cnt;
    if (t == 0) cnt = 0;
    __syncthreads();
    if (t < 256) {
        int match = (eidx[b * SS + t] == iidx[b]);
        coef[t] = match ? pc[b * SS + t] : 0.f;
        if (match) atomicAdd(&cnt, 1);
    }
    __syncthreads();
    float scale = 1.f / (*pcsum);
    if (cnt > 1) scale /= (float)cnt;
    float acc = 0.f;
    const float* eb = enc + (size_t)b * SS * HH + t;
#pragma unroll 4
    for (int s = 0; s < SS; s++) acc += coef[s] * eb[s * HH];
    outw[b * HH + t] = acc * scale;
}

// =========================== launch (single stream) ===========================
extern "C" void kernel_launch(void* const* d_in, const int* in_sizes, int n_in,
                              void* d_out, int out_size)
{
    const int*   input_idx   = (const int*)  d_in[0];
    const float* encoded     = (const float*)d_in[1];
    const int*   encoded_idx = (const int*)  d_in[2];
    const float* prev_state  = (const float*)d_in[3];
    const float* embed_table = (const float*)d_in[5];
    const float* Ws_w        = (const float*)d_in[6];
    const float* Ws_b        = (const float*)d_in[7];
    const float* gru_Wih     = (const float*)d_in[8];
    const float* gru_Whh     = (const float*)d_in[9];
    const float* gru_bih     = (const float*)d_in[10];
    const float* gru_bhh     = (const float*)d_in[11];
    const float* attn_W      = (const float*)d_in[12];
    const float* attn_b      = (const float*)d_in[13];
    const float* attn_v      = (const float*)d_in[14];
    const float* Wo_w        = (const float*)d_in[15];
    const float* Wo_b        = (const float*)d_in[16];
    const float* Wc_w        = (const float*)d_in[17];
    const float* Wc_b        = (const float*)d_in[18];

    float* out          = (float*)d_out;
    float* out_state    = out + (size_t)BB * VEXT;
    float* out_weighted = out_state + BB * HH;

    float* sc = nullptr;
    cudaGetSymbolAddress((void**)&sc, g_scratch);
    float* prev   = sc + OFF_PREV;
    float* gi     = sc + OFF_GI;
    float* gh     = sc + OFF_GH;
    float* satt   = sc + OFF_SATT;
    float* state  = sc + OFF_STATE;
    float* energy = sc + OFF_ENERGY;
    float* yv     = sc + OFF_Y;
    float* scoreg = sc + OFF_SCOREG;
    float* scorec = sc + OFF_SCOREC;
    float* probc  = sc + OFF_PROBC;
    float* invz   = sc + OFF_INVZ;
    float* zrow   = sc + OFF_Z;
    float* pcsum  = sc + OFF_PCSUM;

    cudaFuncSetAttribute(hmma_gemm8, cudaFuncAttributeMaxDynamicSharedMemorySize,
                         V4_DYN);
    cudaFuncSetAttribute(hmma_scores, cudaFuncAttributeMaxDynamicSharedMemorySize,
                         V4_DYN);

    // 1. all zeroing in one launch
    zero_all<<<(NZ + 255) / 256, 256>>>(prev, energy, scorec, invz);
    // 2. prev + gi merged (gather fused into gi A-load)
    gemm_chain1<<<64 + 192, 256>>>(prev_state, Ws_w, Ws_b, prev,
                                   input_idx, embed_table, gru_Wih, gru_bih, gi);
    // 3. gh
    gemm128_splitk<<<dim3(3 * HH / 64, 8), 256>>>(prev, HH, gru_Whh, HH,
                                                  gru_bhh, gh, 3 * HH, HH);
    // 4. GRU
    gru_kernel<<<(BB * HH) / 256, 256>>>(gi, gh, prev, state, yv, out_state);
    // 5. satt
    gemm128_splitk<<<dim3(HH / 64, 8), 256>>>(state, HH, attn_W, 2 * HH,
                                              attn_b, satt, HH, HH);
    // 6. energy GEMM (NT=2)
    hmma_gemm8<<<dim3(256, 2), 256, V4_DYN>>>(
        encoded, 512, 512,
        attn_W, 1024, 512, 512,
        1, satt, 1, 512, attn_v, 0,
        nullptr, 0, energy);
    // 7. attention softmax + context
    softmax_context<<<BB, 512>>>(energy, encoded, yv);
    // 8. merged score_g (NT=2, exp epilogue) + score_c (NT=3)
    hmma_scores<<<NT_G + NT_C, 256, V4_DYN>>>(
        yv, Wo_w, Wo_b, encoded, Wc_w, Wc_b, scoreg, zrow, scorec);
    // 9. finish Z with score_c; probc; invz; pcsum
    probc_z_kernel<<<BB, SS>>>(scorec, encoded_idx, zrow, invz, probc, pcsum);
    // 10. prob_g_ext write (pure multiply)
    finalize_kernel<<<NWG, 256>>>(scoreg, invz, out);
    // 11. scatter + weighted_new merged
    scatter_weighted<<<2 * BB, 512>>>(encoded_idx, input_idx, probc, encoded,
                                      pcsum, out, out_weighted);
}

// round 16
// speedup vs baseline: 1.1746x; 1.0104x over previous
#include <cuda_runtime.h>
#include <cuda_fp16.h>
#include <math.h>
#include <stdint.h>

#define VV 50000
#define EE 512
#define HH 512
#define BB 128
#define SS 256
#define OOV 12
#define VEXT (VV + OOV)   // 50012

// ---------------- fp32 scratch ----------------
#define OFF_PREV   0
#define OFF_GI     (OFF_PREV + BB*HH)
#define OFF_GH     (OFF_GI + BB*3*HH)
#define OFF_SATT   (OFF_GH + BB*3*HH)
#define NZEND      (OFF_SATT + BB*HH)
#define NZ         NZEND
#define OFF_STATE  NZEND
#define OFF_ENERGY (OFF_STATE + BB*HH)
#define OFF_Y      (OFF_ENERGY + BB*SS)
#define OFF_SCOREG (OFF_Y + BB*2*HH)
#define OFF_SCOREC (OFF_SCOREG + (size_t)BB*VV)
#define OFF_PROBC  (OFF_SCOREC + BB*SS)
#define OFF_INVZ   (OFF_PROBC + BB*SS)
#define OFF_Z      (OFF_INVZ + BB)
#define OFF_PCSUM  (OFF_Z + BB)
#define SCRATCH_FLOATS (OFF_PCSUM + 64)

__device__ float g_scratch[SCRATCH_FLOATS];

// ---------------- helpers ----------------
__device__ __forceinline__ uint32_t smem_u32(const void* p) {
    uint32_t a;
    asm("{ .reg .u64 t; cvta.to.shared.u64 t, %1; cvt.u32.u64 %0, t; }"
        : "=r"(a) : "l"(p));
    return a;
}
static __device__ __forceinline__ uint32_t SWZ(uint32_t o) {
    return o ^ ((o >> 3) & 0x70u);
}
__device__ __forceinline__ void cpa16(uint32_t dst, const void* src, int srcsize) {
    asm volatile("cp.async.cg.shared.global [%0], [%1], 16, %2;"
                 :: "r"(dst), "l"(src), "r"(srcsize) : "memory");
}
__device__ __forceinline__ void cpa_commit() {
    asm volatile("cp.async.commit_group;" ::: "memory");
}
__device__ __forceinline__ void cpa_wait0() {
    asm volatile("cp.async.wait_group 0;" ::: "memory");
}
__device__ __forceinline__ void ldm_x4(uint32_t& r0, uint32_t& r1,
                                       uint32_t& r2, uint32_t& r3, uint32_t a) {
    asm volatile("ldmatrix.sync.aligned.m8n8.x4.shared.b16 {%0,%1,%2,%3}, [%4];"
                 : "=r"(r0), "=r"(r1), "=r"(r2), "=r"(r3) : "r"(a));
}
__device__ __forceinline__ void mma16816(float& c0, float& c1, float& c2, float& c3,
                                         uint32_t a0, uint32_t a1, uint32_t a2,
                                         uint32_t a3, uint32_t b0, uint32_t b1) {
    asm volatile("mma.sync.aligned.m16n8k16.row.col.f32.f16.f16.f32 "
                 "{%0,%1,%2,%3}, {%4,%5,%6,%7}, {%8,%9}, {%0,%1,%2,%3};"
                 : "+f"(c0), "+f"(c1), "+f"(c2), "+f"(c3)
                 : "r"(a0), "r"(a1), "r"(a2), "r"(a3), "r"(b0), "r"(b1));
}
// fast tanh: 1 - 2/(exp(2x)+1); abs err ~1e-7
__device__ __forceinline__ float fast_tanh(float x) {
    float e = __expf(2.f * x);
    return 1.f - __fdividef(2.f, e + 1.f);
}

// ============ HMMA core: fp32 in, NT-term fp16 split, convert/MMA overlap ===
#define V4_SA(p)  ((p) * 16384)
#define V4_SB(p)  (32768 + (p) * 32768)
#define V4_HA(p)  (98304 + (p) * 16384)
#define V4_HB(p)  (131072 + (p) * 32768)
#define V4_ADD    196608
#define V4_WV     197632
#define V4_DYN    (198656 + 1024)

template <int NT>
__device__ __forceinline__ void hmma_core8(
    char* smem,
    const float* __restrict__ A, int lda, int K,
    const float* __restrict__ B, int ldb, int bcol, int Nrows,
    int mode,
    const float* __restrict__ addg, int add_per_b, int Ntot,
    const float* __restrict__ wvg, int wv_per_b,
    float* __restrict__ outS, int ldout,
    float* __restrict__ outv,
    int row0, int n0)
{
    constexpr int NJ = 8;
    const uint32_t sb = smem_u32(smem);
    const int tid = threadIdx.x, wid = tid >> 5, lid = tid & 31;
    const int b    = row0 >> 8;
    const int wm0  = (wid >> 2) * 64;
    const int wn0  = (wid & 3) * (NJ * 8);
    constexpr int TOT = 4 + NJ;

    float* add_s = (float*)(smem + V4_ADD);
    float* wv_s  = (float*)(smem + V4_WV);
    {
        int gn = n0 + tid;
        if (mode != 1) {
            add_s[tid] = (gn < Nrows) ? addg[gn] : 0.f;
        } else {
            add_s[tid] = add_per_b ? addg[(size_t)b * Ntot + gn] : addg[gn];
            wv_s[tid]  = wv_per_b ? wvg[(size_t)b * Ntot + gn] : wvg[gn];
        }
    }

    const int nc = K >> 5;

    auto issue = [&](int c, int par) {
        int k0 = c << 5;
#pragma unroll
        for (int i = 0; i < 4; i++) {
            int u = tid + i * 256;
            int r = u >> 3, b16 = u & 7;
            cpa16(sb + V4_SA(par) + (uint32_t)(r * 128 + b16 * 16),
                  &A[(size_t)(row0 + r) * lda + k0 + b16 * 4], 16);
        }
#pragma unroll
        for (int i = 0; i < NJ; i++) {
            int u = tid + i * 256;
            int r = u >> 3, b16 = u & 7;
            int gr = n0 + r;
            int ok = (gr < Nrows) ? 16 : 0;
            int grc = (gr < Nrows) ? gr : 0;
            cpa16(sb + V4_SB(par) + (uint32_t)(r * 128 + b16 * 16),
                  &B[(size_t)grc * ldb + bcol + k0 + b16 * 4], ok);
        }
        cpa_commit();
    };

    auto conv_range = [&](int par, int i0, int i1) {
        for (int i = i0; i < i1; i++) {
            int stage_off, h_off, idx;
            bool isA = (i < 4);
            if (isA) { idx = tid + i * 256; stage_off = V4_SA(par); h_off = V4_HA(par); }
            else     { idx = tid + (i - 4) * 256; stage_off = V4_SB(par); h_off = V4_HB(par); }
            int r = idx >> 3, c4 = idx & 7;
            float4 v = *(const float4*)(smem + stage_off + r * 128 + c4 * 16);
            __half2 h01 = __float22half2_rn(make_float2(v.x, v.y));
            __half2 h23 = __float22half2_rn(make_float2(v.z, v.w));
            uint2 hv = make_uint2(*(uint32_t*)&h01, *(uint32_t*)&h23);
            *(uint2*)(smem + h_off + SWZ((uint32_t)(r * 128 + c4 * 8))) = hv;
            if (isA || NT == 3) {
                float2 f01 = __half22float2(h01);
                float2 f23 = __half22float2(h23);
                __half2 l01 = __float22half2_rn(make_float2(v.x - f01.x, v.y - f01.y));
                __half2 l23 = __float22half2_rn(make_float2(v.z - f23.x, v.w - f23.y));
                uint2 lv = make_uint2(*(uint32_t*)&l01, *(uint32_t*)&l23);
                *(uint2*)(smem + h_off + SWZ((uint32_t)(r * 128 + 64 + c4 * 8))) = lv;
            }
        }
    };

    float cacc[4][NJ][4];
#pragma unroll
    for (int mi = 0; mi < 4; mi++)
#pragma unroll
        for (int nj = 0; nj < NJ; nj++)
#pragma unroll
            for (int f = 0; f < 4; f++) cacc[mi][nj][f] = 0.f;

    const int a_row  = wm0 + (lid & 15);
    const int a_csel = ((lid >> 4) & 1) * 16;
    const int b_rowo = (lid & 7) + ((lid >> 4) & 1) * 8;
    const int b_csel = ((lid >> 3) & 1) * 16;

    issue(0, 0);
    cpa_wait0();
    conv_range(0, 0, TOT);
    if (nc > 1) issue(1, 1);
    __syncthreads();

    constexpr int NSG = 2 * NT;
    for (int c = 0; c < nc; c++) {
        const int par = c & 1;
        const bool more = (c + 1 < nc);
        if (more) {
            cpa_wait0();
            if (c + 2 < nc) issue(c + 2, par);
        }
        const uint32_t ha = sb + V4_HA(par);
        const uint32_t hb = sb + V4_HB(par);
#pragma unroll
        for (int sg = 0; sg < NSG; sg++) {
            const int t = sg >> 1, k16 = sg & 1;
            const int aoff = (t == 1) ? 64 : 0;
            const int boff = (t == 2) ? 64 : 0;
            uint32_t a[4][4];
#pragma unroll
            for (int mi = 0; mi < 4; mi++) {
                uint32_t addr = ha + SWZ((uint32_t)((a_row + mi * 16) * 128 +
                                                    aoff + k16 * 32 + a_csel));
                ldm_x4(a[mi][0], a[mi][1], a[mi][2], a[mi][3], addr);
            }
            uint32_t bf[NJ][2];
#pragma unroll
            for (int nj2 = 0; nj2 < NJ / 2; nj2++) {
                uint32_t addr = hb + SWZ((uint32_t)((wn0 + nj2 * 16 + b_rowo) * 128 +
                                                    boff + k16 * 32 + b_csel));
                ldm_x4(bf[2 * nj2][0], bf[2 * nj2][1],
                       bf[2 * nj2 + 1][0], bf[2 * nj2 + 1][1], addr);
            }
            if (more) conv_range(par ^ 1, (TOT * sg) / NSG, (TOT * (sg + 1)) / NSG);
#pragma unroll
            for (int mi = 0; mi < 4; mi++)
#pragma unroll
                for (int nj = 0; nj < NJ; nj++)
                    mma16816(cacc[mi][nj][0], cacc[mi][nj][1],
                             cacc[mi][nj][2], cacc[mi][nj][3],
                             a[mi][0], a[mi][1], a[mi][2], a[mi][3],
                             bf[nj][0], bf[nj][1]);
        }
        if (more) __syncthreads();
    }

    const int rA = wm0 + (lid >> 2);
    const int lcol = wn0 + 2 * (lid & 3);
    if (mode == 0) {
#pragma unroll
        for (int mi = 0; mi < 4; mi++) {
#pragma unroll
            for (int nj = 0; nj < NJ; nj++) {
                int lc = lcol + nj * 8;
                int n = n0 + lc;
                if (n < Nrows) {
                    int r0r = row0 + rA + mi * 16;
                    float2 v0 = make_float2(cacc[mi][nj][0] + add_s[lc],
                                            cacc[mi][nj][1] + add_s[lc + 1]);
                    float2 v1 = make_float2(cacc[mi][nj][2] + add_s[lc],
                                            cacc[mi][nj][3] + add_s[lc + 1]);
                    *(float2*)&outS[(size_t)r0r * ldout + n] = v0;
                    *(float2*)&outS[(size_t)(r0r + 8) * ldout + n] = v1;
                }
            }
        }
    } else if (mode == 2) {
#pragma unroll
        for (int mi = 0; mi < 4; mi++) {
            float s0 = 0.f, s1 = 0.f;
#pragma unroll
            for (int nj = 0; nj < NJ; nj++) {
                int lc = lcol + nj * 8;
                int n = n0 + lc;
                if (n < Nrows) {
                    float e0 = __expf(cacc[mi][nj][0] + add_s[lc]);
                    float e1 = __expf(cacc[mi][nj][1] + add_s[lc + 1]);
                    float e2 = __expf(cacc[mi][nj][2] + add_s[lc]);
                    float e3 = __expf(cacc[mi][nj][3] + add_s[lc + 1]);
                    int r0r = row0 + rA + mi * 16;
                    *(float2*)&outS[(size_t)r0r * ldout + n] = make_float2(e0, e1);
                    *(float2*)&outS[(size_t)(r0r + 8) * ldout + n] = make_float2(e2, e3);
                    s0 += e0 + e1;
                    s1 += e2 + e3;
                }
            }
            s0 += __shfl_xor_sync(0xffffffffu, s0, 1);
            s0 += __shfl_xor_sync(0xffffffffu, s0, 2);
            s1 += __shfl_xor_sync(0xffffffffu, s1, 1);
            s1 += __shfl_xor_sync(0xffffffffu, s1, 2);
            if ((lid & 3) == 0) {
                atomicAdd(&outv[row0 + rA + mi * 16], s0);
                atomicAdd(&outv[row0 + rA + mi * 16 + 8], s1);
            }
        }
    } else {
#pragma unroll
        for (int mi = 0; mi < 4; mi++) {
            float p0 = 0.f, p1 = 0.f;
#pragma unroll
            for (int nj = 0; nj < NJ; nj++) {
                int lc = lcol + nj * 8;
                float ad0 = add_s[lc], ad1 = add_s[lc + 1];
                float w0 = wv_s[lc],  w1 = wv_s[lc + 1];
                p0 += fast_tanh(cacc[mi][nj][0] + ad0) * w0
                    + fast_tanh(cacc[mi][nj][1] + ad1) * w1;
                p1 += fast_tanh(cacc[mi][nj][2] + ad0) * w0
                    + fast_tanh(cacc[mi][nj][3] + ad1) * w1;
            }
            p0 += __shfl_xor_sync(0xffffffffu, p0, 1);
            p0 += __shfl_xor_sync(0xffffffffu, p0, 2);
            p1 += __shfl_xor_sync(0xffffffffu, p1, 1);
            p1 += __shfl_xor_sync(0xffffffffu, p1, 2);
            if ((lid & 3) == 0) {
                atomicAdd(&outv[row0 + rA + mi * 16], p0);
                atomicAdd(&outv[row0 + rA + mi * 16 + 8], p1);
            }
        }
    }
}

// ---- energy GEMM: NT=2 ----
__global__ __launch_bounds__(256)
void hmma_gemm8(const float* __restrict__ A, int lda, int K,
                const float* __restrict__ B, int ldb, int bcol, int Nrows,
                int mode,
                const float* __restrict__ addg, int add_per_b, int Ntot,
                const float* __restrict__ wvg, int wv_per_b,
                float* __restrict__ outS, int ldout,
                float* __restrict__ outv)
{
    extern __shared__ char smem_raw[];
    char* smem = (char*)(((uintptr_t)smem_raw + 1023) & ~(uintptr_t)1023);
    hmma_core8<2>(smem, A, lda, K, B, ldb, bcol, Nrows, mode,
                  addg, add_per_b, Ntot, wvg, wv_per_b, outS, ldout, outv,
                  blockIdx.x * 128, blockIdx.y * 256);
}

// ---- merged score_g(exp, NT=2) + score_c(NT=3) GEMM ----
#define NT_G 196
#define NT_C 1024
__global__ __launch_bounds__(256)
void hmma_scores(const float* __restrict__ yv,
                 const float* __restrict__ Wo, const float* __restrict__ Wob,
                 const float* __restrict__ enc,
                 const float* __restrict__ Wc, const float* __restrict__ Wcb,
                 float* __restrict__ scoregE, float* __restrict__ zrow,
                 float* __restrict__ scorec)
{
    extern __shared__ char smem_raw[];
    char* smem = (char*)(((uintptr_t)smem_raw + 1023) & ~(uintptr_t)1023);
    int tile = blockIdx.x;
    if (tile < NT_G) {
        hmma_core8<2>(smem, yv, 1024, 1024, Wo, 1024, 0, VV, 2,
                      Wob, 0, 0, nullptr, 0, scoregE, VV, zrow,
                      0, tile * 256);
    } else {
        int t2 = tile - NT_G;
        hmma_core8<3>(smem, enc, 512, 512, Wc, 512, 0, 1024, 1,
                      Wcb, 0, 1024, yv, 1, nullptr, 0, scorec,
                      (t2 >> 2) * 128, (t2 & 3) * 256);
    }
}

// ================= FFMA2 small GEMM =================
__device__ __forceinline__ void ffma2(unsigned long long &c,
                                      unsigned long long a,
                                      unsigned long long b) {
    asm("fma.rn.f32x2 %0, %1, %2, %0;" : "+l"(c) : "l"(a), "l"(b));
}
struct __align__(16) ull2 { unsigned long long x, y; };
__device__ __forceinline__ float f2lo(unsigned long long v) {
    return __uint_as_float((unsigned int)v);
}
__device__ __forceinline__ float f2hi(unsigned long long v) {
    return __uint_as_float((unsigned int)(v >> 32));
}
__device__ __forceinline__ unsigned long long dupf(float v) {
    unsigned int u = __float_as_uint(v);
    unsigned long long r;
    asm("mov.b64 %0, {%1, %1};" : "=l"(r) : "r"(u));
    return r;
}
#define K16_FFMA2_LOOP(acc, Asm, Wsm, ty, tx)                                 \
    _Pragma("unroll")                                                         \
    for (int kk = 0; kk < 16; kk++) {                                         \
        ull2 a01 = *(const ull2*)&Asm[kk][(ty) * 8];                          \
        ull2 a23 = *(const ull2*)&Asm[kk][(ty) * 8 + 4];                      \
        float4 wq = *(const float4*)&Wsm[kk][(tx) * 4];                       \
        unsigned long long w0 = dupf(wq.x), w1 = dupf(wq.y);                  \
        unsigned long long w2 = dupf(wq.z), w3 = dupf(wq.w);                  \
        ffma2(acc[0][0], a01.x, w0); ffma2(acc[0][1], a01.x, w1);             \
        ffma2(acc[0][2], a01.x, w2); ffma2(acc[0][3], a01.x, w3);             \
        ffma2(acc[1][0], a01.y, w0); ffma2(acc[1][1], a01.y, w1);             \
        ffma2(acc[1][2], a01.y, w2); ffma2(acc[1][3], a01.y, w3);             \
        ffma2(acc[2][0], a23.x, w0); ffma2(acc[2][1], a23.x, w1);             \
        ffma2(acc[2][2], a23.x, w2); ffma2(acc[2][3], a23.x, w3);             \
        ffma2(acc[3][0], a23.y, w0); ffma2(acc[3][1], a23.y, w1);             \
        ffma2(acc[3][2], a23.y, w2); ffma2(acc[3][3], a23.y, w3);             \
    }

__device__ __forceinline__ void gemm128_core(
    const float* __restrict__ A, int lda, const int* __restrict__ aidx,
    const float* __restrict__ W, int ldw, const float* __restrict__ bias,
    float* __restrict__ C, int N, int n0, int ks, int kl, bool addbias)
{
    __shared__ float Asm[16][132];
    __shared__ float Wsm[16][68];
    const int tid = threadIdx.x;
    const int ty = tid >> 4, tx = tid & 15;
    const int am  = tid >> 2;
    const int akv = (tid & 3) << 2;

    unsigned long long acc[4][4];
#pragma unroll
    for (int i = 0; i < 4; i++)
#pragma unroll
        for (int j = 0; j < 4; j++) acc[i][j] = 0ull;

    for (int k0 = ks; k0 < ks + kl; k0 += 16) {
        __syncthreads();
#pragma unroll
        for (int r = 0; r < 2; r++) {
            int m = am + r * 64;
            long arow = aidx ? (long)aidx[m] : (long)m;
            float4 v = *(const float4*)&A[arow * lda + k0 + akv];
            Asm[akv+0][m] = v.x; Asm[akv+1][m] = v.y;
            Asm[akv+2][m] = v.z; Asm[akv+3][m] = v.w;
        }
        {
            float4 v = *(const float4*)&W[(size_t)(n0 + am) * ldw + k0 + akv];
            Wsm[akv+0][am] = v.x; Wsm[akv+1][am] = v.y;
            Wsm[akv+2][am] = v.z; Wsm[akv+3][am] = v.w;
        }
        __syncthreads();
        K16_FFMA2_LOOP(acc, Asm, Wsm, ty, tx)
    }
#pragma unroll
    for (int r2 = 0; r2 < 4; r2++) {
#pragma unroll
        for (int j = 0; j < 4; j++) {
            int n = n0 + tx * 4 + j;
            float bsum = (addbias && bias) ? bias[n] : 0.f;
            int m0 = ty * 8 + 2 * r2;
            atomicAdd(&C[(size_t)m0 * N + n],       f2lo(acc[r2][j]) + bsum);
            atomicAdd(&C[(size_t)(m0 + 1) * N + n], f2hi(acc[r2][j]) + bsum);
        }
    }
}

__global__ __launch_bounds__(256)
void gemm128_splitk(const float* __restrict__ A, int lda,
                    const float* __restrict__ W, int ldw,
                    const float* __restrict__ bias,
                    float* __restrict__ C, int N, int Ktot)
{
    int kl = Ktot / gridDim.y;
    gemm128_core(A, lda, nullptr, W, ldw, bias, C, N,
                 blockIdx.x * 64, blockIdx.y * kl, kl, blockIdx.y == 0);
}

// merged: prev = prev_state@Ws^T + Ws_b  AND  gi = embed[idx]@Wih[:, :E]^T + bih
__global__ __launch_bounds__(256)
void gemm_chain1(const float* __restrict__ prev_state,
                 const float* __restrict__ Ws_w, const float* __restrict__ Ws_b,
                 float* __restrict__ prev,
                 const int* __restrict__ input_idx,
                 const float* __restrict__ embed_table,
                 const float* __restrict__ gru_Wih,
                 const float* __restrict__ gru_bih,
                 float* __restrict__ gi)
{
    int bx = blockIdx.x;
    if (bx < 64) {
        int n0 = (bx & 7) * 64, kb = bx >> 3;
        gemm128_core(prev_state, HH, nullptr, Ws_w, HH, Ws_b, prev, HH,
                     n0, kb * 64, 64, kb == 0);
    } else {
        bx -= 64;
        int n0 = (bx % 24) * 64, kb = bx / 24;
        gemm128_core(embed_table, EE, input_idx, gru_Wih, EE + HH, gru_bih,
                     gi, 3 * HH, n0, kb * 64, 64, kb == 0);
    }
}

// zero split-K accumulators + energy + scorec + zrow/invz/pcsum (float4)
__global__ __launch_bounds__(256)
void zero_all(float4* __restrict__ base, float4* __restrict__ energy,
              float4* __restrict__ scorec, float* __restrict__ tailz)
{
    int i = blockIdx.x * 256 + threadIdx.x;
    float4 z4 = make_float4(0.f, 0.f, 0.f, 0.f);
    if (i < NZ / 4) base[i] = z4;
    if (i < (BB * SS) / 4) { energy[i] = z4; scorec[i] = z4; }
    if (i < 2 * BB + 1) tailz[i] = 0.f;   // invz, zrow, pcsum
}

__global__ __launch_bounds__(256)
void gru_kernel(const float* __restrict__ gi, const float* __restrict__ gh,
                const float* __restrict__ prev,
                float* __restrict__ state, float* __restrict__ y,
                float* __restrict__ out_state)
{
    int i = blockIdx.x * 256 + threadIdx.x;
    int b = i / HH, h = i - b * HH;
    const float* gib = gi + b * 3 * HH;
    const float* ghb = gh + b * 3 * HH;
    float i_r = gib[h],          h_r = ghb[h];
    float i_z = gib[HH + h],     h_z = ghb[HH + h];
    float i_n = gib[2 * HH + h], h_n = ghb[2 * HH + h];
    float r = 1.f / (1.f + expf(-(i_r + h_r)));
    float z = 1.f / (1.f + expf(-(i_z + h_z)));
    float n = tanhf(i_n + r * h_n);
    float st = (1.f - z) * n + z * prev[i];
    state[i] = st;
    y[b * (2 * HH) + h] = st;
    out_state[i] = st;
}

// fused attention softmax + context
__global__ __launch_bounds__(512)
void softmax_context(const float* __restrict__ e, const float* __restrict__ enc,
                     float* __restrict__ y)
{
    int b = blockIdx.x, t = threadIdx.x;
    __shared__ float sm[256];
    __shared__ float c[256];
    float x = 0.f;
    if (t < 256) { x = e[b * SS + t]; sm[t] = x; }
    __syncthreads();
    for (int o = 128; o > 0; o >>= 1) {
        if (t < o) sm[t] = fmaxf(sm[t], sm[t + o]);
        __syncthreads();
    }
    float mx = sm[0];
    __syncthreads();
    float ex = 0.f;
    if (t < 256) { ex = expf(x - mx); sm[t] = ex; }
    __syncthreads();
    for (int o = 128; o > 0; o >>= 1) {
        if (t < o) sm[t] += sm[t + o];
        __syncthreads();
    }
    float Z = sm[0];
    __syncthreads();
    if (t < 256) c[t] = ex / Z;
    __syncthreads();
    float acc = 0.f;
    const float* eb = enc + (size_t)b * SS * HH + t;
#pragma unroll 4
    for (int s = 0; s < SS; s++) acc += c[s] * eb[s * HH];
    y[b * (2 * HH) + HH + t] = acc;
}

// finish Z with score_c exps; probc = ec/Z; invz; pcsum; scatter ec into E
__global__ __launch_bounds__(256)
void probc_z_kernel(const float* __restrict__ c, const int* __restrict__ eidx,
                    float* __restrict__ zrow, float* __restrict__ invz,
                    float* __restrict__ pc, float* __restrict__ pcsum,
                    float* __restrict__ E)
{
    int b = blockIdx.x, t = threadIdx.x;
    int e = eidx[b * SS + t];
    float x = c[b * SS + t] + ((e == 0) ? -1000.f : 0.f);
    float ec = __expf(x);
    // fold the prob_c scatter: out = (E + sum ec)*invZ  (e < VV always)
    atomicAdd(&E[(size_t)b * VV + e], ec);
    __shared__ float sm[256];
    __shared__ float iZs;
    sm[t] = ec; __syncthreads();
    for (int o = 128; o > 0; o >>= 1) { if (t < o) sm[t] += sm[t + o]; __syncthreads(); }
    if (t == 0) {
        float Z = zrow[b] + sm[0];
        float iZ = 1.f / Z;
        iZs = iZ;
        invz[b] = iZ;
        atomicAdd(pcsum, sm[0] * iZ);
    }
    __syncthreads();
    pc[b * SS + t] = ec * iZs;
}

// prob_g_ext write (float4): out = E * invZ  (scatter already folded into E)
#define NW4 ((BB * VEXT) / 4)         // 1600384 float4, exact
#define ROW4 (VEXT / 4)               // 12503
#define VV4  (VV / 4)                 // 12500
__global__ __launch_bounds__(256)
void finalize_kernel(const float4* __restrict__ E, const float* __restrict__ invz,
                     float4* __restrict__ out)
{
    int i = blockIdx.x * 256 + threadIdx.x;
    if (i >= NW4) return;
    int b = i / ROW4;
    int j4 = i - b * ROW4;
    if (j4 < VV4) {
        float iZ = invz[b];
        float4 v = E[(size_t)b * VV4 + j4];
        out[i] = make_float4(v.x * iZ, v.y * iZ, v.z * iZ, v.w * iZ);
    } else {
        out[i] = make_float4(1e-4f, 1e-4f, 1e-4f, 1e-4f);
    }
}

// weighted_new only (scatter folded into probc_z)
__global__ __launch_bounds__(512)
void weighted_kernel(const int* __restrict__ eidx, const int* __restrict__ iidx,
                     const float* __restrict__ pc, const float* __restrict__ enc,
                     const float* __restrict__ pcsum, float* __restrict__ outw)
{
    int b = blockIdx.x, t = threadIdx.x;
    __shared__ float coef[256];
    __shared__ int cnt;
    if (t == 0) cnt = 0;
    __syncthreads();
    if (t < 256) {
        int match = (eidx[b * SS + t] == iidx[b]);
        coef[t] = match ? pc[b * SS + t] : 0.f;
        if (match) atomicAdd(&cnt, 1);
    }
    __syncthreads();
    float scale = 1.f / (*pcsum);
    if (cnt > 1) scale /= (float)cnt;
    float acc = 0.f;
    const float* eb = enc + (size_t)b * SS * HH + t;
#pragma unroll 4
    for (int s = 0; s < SS; s++) acc += coef[s] * eb[s * HH];
    outw[b * HH + t] = acc * scale;
}

// =========================== launch (single stream) ===========================
extern "C" void kernel_launch(void* const* d_in, const int* in_sizes, int n_in,
                              void* d_out, int out_size)
{
    const int*   input_idx   = (const int*)  d_in[0];
    const float* encoded     = (const float*)d_in[1];
    const int*   encoded_idx = (const int*)  d_in[2];
    const float* prev_state  = (const float*)d_in[3];
    const float* embed_table = (const float*)d_in[5];
    const float* Ws_w        = (const float*)d_in[6];
    const float* Ws_b        = (const float*)d_in[7];
    const float* gru_Wih     = (const float*)d_in[8];
    const float* gru_Whh     = (const float*)d_in[9];
    const float* gru_bih     = (const float*)d_in[10];
    const float* gru_bhh     = (const float*)d_in[11];
    const float* attn_W      = (const float*)d_in[12];
    const float* attn_b      = (const float*)d_in[13];
    const float* attn_v      = (const float*)d_in[14];
    const float* Wo_w        = (const float*)d_in[15];
    const float* Wo_b        = (const float*)d_in[16];
    const float* Wc_w        = (const float*)d_in[17];
    const float* Wc_b        = (const float*)d_in[18];

    float* out          = (float*)d_out;
    float* out_state    = out + (size_t)BB * VEXT;
    float* out_weighted = out_state + BB * HH;

    float* sc = nullptr;
    cudaGetSymbolAddress((void**)&sc, g_scratch);
    float* prev   = sc + OFF_PREV;
    float* gi     = sc + OFF_GI;
    float* gh     = sc + OFF_GH;
    float* satt   = sc + OFF_SATT;
    float* state  = sc + OFF_STATE;
    float* energy = sc + OFF_ENERGY;
    float* yv     = sc + OFF_Y;
    float* scoreg = sc + OFF_SCOREG;
    float* scorec = sc + OFF_SCOREC;
    float* probc  = sc + OFF_PROBC;
    float* invz   = sc + OFF_INVZ;
    float* zrow   = sc + OFF_Z;
    float* pcsum  = sc + OFF_PCSUM;

    cudaFuncSetAttribute(hmma_gemm8, cudaFuncAttributeMaxDynamicSharedMemorySize,
                         V4_DYN);
    cudaFuncSetAttribute(hmma_scores, cudaFuncAttributeMaxDynamicSharedMemorySize,
                         V4_DYN);

    // 1. all zeroing in one launch (float4)
    zero_all<<<(NZ / 4 + 255) / 256, 256>>>((float4*)prev, (float4*)energy,
                                            (float4*)scorec, invz);
    // 2. prev + gi merged (gather fused into gi A-load)
    gemm_chain1<<<64 + 192, 256>>>(prev_state, Ws_w, Ws_b, prev,
                                   input_idx, embed_table, gru_Wih, gru_bih, gi);
    // 3. gh
    gemm128_splitk<<<dim3(3 * HH / 64, 8), 256>>>(prev, HH, gru_Whh, HH,
                                                  gru_bhh, gh, 3 * HH, HH);
    // 4. GRU
    gru_kernel<<<(BB * HH) / 256, 256>>>(gi, gh, prev, state, yv, out_state);
    // 5. satt
    gemm128_splitk<<<dim3(HH / 64, 8), 256>>>(state, HH, attn_W, 2 * HH,
                                              attn_b, satt, HH, HH);
    // 6. energy GEMM (NT=2)
    hmma_gemm8<<<dim3(256, 2), 256, V4_DYN>>>(
        encoded, 512, 512,
        attn_W, 1024, 512, 512,
        1, satt, 1, 512, attn_v, 0,
        nullptr, 0, energy);
    // 7. attention softmax + context
    softmax_context<<<BB, 512>>>(energy, encoded, yv);
    // 8. merged score_g (NT=2, exp epilogue) + score_c (NT=3)
    hmma_scores<<<NT_G + NT_C, 256, V4_DYN>>>(
        yv, Wo_w, Wo_b, encoded, Wc_w, Wc_b, scoreg, zrow, scorec);
    // 9. finish Z; probc; invz; pcsum; scatter ec into E
    probc_z_kernel<<<BB, SS>>>(scorec, encoded_idx, zrow, invz, probc, pcsum,
                               scoreg);
    // 10. prob_g_ext + scattered copy probs, one vectorized multiply
    finalize_kernel<<<(NW4 + 255) / 256, 256>>>((const float4*)scoreg, invz,
                                                (float4*)out);
    // 11. weighted_new
    weighted_kernel<<<BB, 512>>>(encoded_idx, input_idx, probc, encoded,
                                 pcsum, out_weighted);
}

// round 17
// speedup vs baseline: 1.2716x; 1.0825x over previous
#include <cuda_runtime.h>
#include <cuda_fp16.h>
#include <math.h>
#include <stdint.h>

#define VV 50000
#define EE 512
#define HH 512
#define BB 128
#define SS 256
#define OOV 12
#define VEXT (VV + OOV)   // 50012

// ---------------- fp32 scratch ----------------
#define OFF_PREV   0
#define OFF_GI     (OFF_PREV + BB*HH)
#define OFF_GH     (OFF_GI + BB*3*HH)
#define OFF_SATT   (OFF_GH + BB*3*HH)
#define NZEND      (OFF_SATT + BB*HH)
#define NZ         NZEND
#define OFF_STATE  NZEND
#define OFF_ENERGY (OFF_STATE + BB*HH)
#define OFF_Y      (OFF_ENERGY + BB*SS)
#define OFF_SCOREG (OFF_Y + BB*2*HH)
#define OFF_SCOREC (OFF_SCOREG + (size_t)BB*VV)
#define OFF_PROBC  (OFF_SCOREC + BB*SS)
#define OFF_INVZ   (OFF_PROBC + BB*SS)
#define OFF_Z      (OFF_INVZ + BB)
#define OFF_PCSUM  (OFF_Z + BB)
#define SCRATCH_FLOATS (OFF_PCSUM + 64)

__device__ float g_scratch[SCRATCH_FLOATS];

// ---------------- helpers ----------------
__device__ __forceinline__ uint32_t smem_u32(const void* p) {
    uint32_t a;
    asm("{ .reg .u64 t; cvta.to.shared.u64 t, %1; cvt.u32.u64 %0, t; }"
        : "=r"(a) : "l"(p));
    return a;
}
static __device__ __forceinline__ uint32_t SWZ(uint32_t o) {
    return o ^ ((o >> 3) & 0x70u);
}
__device__ __forceinline__ void cpa16(uint32_t dst, const void* src, int srcsize) {
    asm volatile("cp.async.cg.shared.global [%0], [%1], 16, %2;"
                 :: "r"(dst), "l"(src), "r"(srcsize) : "memory");
}
__device__ __forceinline__ void cpa_commit() {
    asm volatile("cp.async.commit_group;" ::: "memory");
}
__device__ __forceinline__ void cpa_wait0() {
    asm volatile("cp.async.wait_group 0;" ::: "memory");
}
__device__ __forceinline__ void ldm_x4(uint32_t& r0, uint32_t& r1,
                                       uint32_t& r2, uint32_t& r3, uint32_t a) {
    asm volatile("ldmatrix.sync.aligned.m8n8.x4.shared.b16 {%0,%1,%2,%3}, [%4];"
                 : "=r"(r0), "=r"(r1), "=r"(r2), "=r"(r3) : "r"(a));
}
__device__ __forceinline__ void mma16816(float& c0, float& c1, float& c2, float& c3,
                                         uint32_t a0, uint32_t a1, uint32_t a2,
                                         uint32_t a3, uint32_t b0, uint32_t b1) {
    asm volatile("mma.sync.aligned.m16n8k16.row.col.f32.f16.f16.f32 "
                 "{%0,%1,%2,%3}, {%4,%5,%6,%7}, {%8,%9}, {%0,%1,%2,%3};"
                 : "+f"(c0), "+f"(c1), "+f"(c2), "+f"(c3)
                 : "r"(a0), "r"(a1), "r"(a2), "r"(a3), "r"(b0), "r"(b1));
}
// fast tanh: 1 - 2/(exp(2x)+1); abs err ~1e-7
__device__ __forceinline__ float fast_tanh(float x) {
    float e = __expf(2.f * x);
    return 1.f - __fdividef(2.f, e + 1.f);
}

// ============ HMMA core: fp32 in, NT-term fp16 split, convert/MMA overlap ===
// NT=3: Ah.Bh + Al.Bh + Ah.Bl (~2^-22). NT=2: A.Bh (~2^-12 on B).
// NT=1: Ah.Bh (~2^-12 on A and B, sqrt(2) x NT=2 error).
#define V4_SA(p)  ((p) * 16384)
#define V4_SB(p)  (32768 + (p) * 32768)
#define V4_HA(p)  (98304 + (p) * 16384)
#define V4_HB(p)  (131072 + (p) * 32768)
#define V4_ADD    196608
#define V4_WV     197632
#define V4_DYN    (198656 + 1024)

template <int NT>
__device__ __forceinline__ void hmma_core8(
    char* smem,
    const float* __restrict__ A, int lda, int K,
    const float* __restrict__ B, int ldb, int bcol, int Nrows,
    int mode,
    const float* __restrict__ addg, int add_per_b, int Ntot,
    const float* __restrict__ wvg, int wv_per_b,
    float* __restrict__ outS, int ldout,
    float* __restrict__ outv,
    int row0, int n0)
{
    constexpr int NJ = 8;
    const uint32_t sb = smem_u32(smem);
    const int tid = threadIdx.x, wid = tid >> 5, lid = tid & 31;
    const int b    = row0 >> 8;
    const int wm0  = (wid >> 2) * 64;
    const int wn0  = (wid & 3) * (NJ * 8);
    constexpr int TOT = 4 + NJ;

    float* add_s = (float*)(smem + V4_ADD);
    float* wv_s  = (float*)(smem + V4_WV);
    {
        int gn = n0 + tid;
        if (mode != 1) {
            add_s[tid] = (gn < Nrows) ? addg[gn] : 0.f;
        } else {
            add_s[tid] = add_per_b ? addg[(size_t)b * Ntot + gn] : addg[gn];
            wv_s[tid]  = wv_per_b ? wvg[(size_t)b * Ntot + gn] : wvg[gn];
        }
    }

    const int nc = K >> 5;

    auto issue = [&](int c, int par) {
        int k0 = c << 5;
#pragma unroll
        for (int i = 0; i < 4; i++) {
            int u = tid + i * 256;
            int r = u >> 3, b16 = u & 7;
            cpa16(sb + V4_SA(par) + (uint32_t)(r * 128 + b16 * 16),
                  &A[(size_t)(row0 + r) * lda + k0 + b16 * 4], 16);
        }
#pragma unroll
        for (int i = 0; i < NJ; i++) {
            int u = tid + i * 256;
            int r = u >> 3, b16 = u & 7;
            int gr = n0 + r;
            int ok = (gr < Nrows) ? 16 : 0;
            int grc = (gr < Nrows) ? gr : 0;
            cpa16(sb + V4_SB(par) + (uint32_t)(r * 128 + b16 * 16),
                  &B[(size_t)grc * ldb + bcol + k0 + b16 * 4], ok);
        }
        cpa_commit();
    };

    auto conv_range = [&](int par, int i0, int i1) {
        for (int i = i0; i < i1; i++) {
            int stage_off, h_off, idx;
            bool isA = (i < 4);
            if (isA) { idx = tid + i * 256; stage_off = V4_SA(par); h_off = V4_HA(par); }
            else     { idx = tid + (i - 4) * 256; stage_off = V4_SB(par); h_off = V4_HB(par); }
            int r = idx >> 3, c4 = idx & 7;
            float4 v = *(const float4*)(smem + stage_off + r * 128 + c4 * 16);
            __half2 h01 = __float22half2_rn(make_float2(v.x, v.y));
            __half2 h23 = __float22half2_rn(make_float2(v.z, v.w));
            uint2 hv = make_uint2(*(uint32_t*)&h01, *(uint32_t*)&h23);
            *(uint2*)(smem + h_off + SWZ((uint32_t)(r * 128 + c4 * 8))) = hv;
            if ((isA && NT >= 2) || NT == 3) {   // lo: A if NT>=2, B if NT=3
                float2 f01 = __half22float2(h01);
                float2 f23 = __half22float2(h23);
                __half2 l01 = __float22half2_rn(make_float2(v.x - f01.x, v.y - f01.y));
                __half2 l23 = __float22half2_rn(make_float2(v.z - f23.x, v.w - f23.y));
                uint2 lv = make_uint2(*(uint32_t*)&l01, *(uint32_t*)&l23);
                *(uint2*)(smem + h_off + SWZ((uint32_t)(r * 128 + 64 + c4 * 8))) = lv;
            }
        }
    };

    float cacc[4][NJ][4];
#pragma unroll
    for (int mi = 0; mi < 4; mi++)
#pragma unroll
        for (int nj = 0; nj < NJ; nj++)
#pragma unroll
            for (int f = 0; f < 4; f++) cacc[mi][nj][f] = 0.f;

    const int a_row  = wm0 + (lid & 15);
    const int a_csel = ((lid >> 4) & 1) * 16;
    const int b_rowo = (lid & 7) + ((lid >> 4) & 1) * 8;
    const int b_csel = ((lid >> 3) & 1) * 16;

    issue(0, 0);
    cpa_wait0();
    conv_range(0, 0, TOT);
    if (nc > 1) issue(1, 1);
    __syncthreads();

    constexpr int NSG = 2 * NT;
    for (int c = 0; c < nc; c++) {
        const int par = c & 1;
        const bool more = (c + 1 < nc);
        if (more) {
            cpa_wait0();
            if (c + 2 < nc) issue(c + 2, par);
        }
        const uint32_t ha = sb + V4_HA(par);
        const uint32_t hb = sb + V4_HB(par);
#pragma unroll
        for (int sg = 0; sg < NSG; sg++) {
            const int t = sg >> 1, k16 = sg & 1;
            const int aoff = (t == 1) ? 64 : 0;
            const int boff = (t == 2) ? 64 : 0;
            uint32_t a[4][4];
#pragma unroll
            for (int mi = 0; mi < 4; mi++) {
                uint32_t addr = ha + SWZ((uint32_t)((a_row + mi * 16) * 128 +
                                                    aoff + k16 * 32 + a_csel));
                ldm_x4(a[mi][0], a[mi][1], a[mi][2], a[mi][3], addr);
            }
            uint32_t bf[NJ][2];
#pragma unroll
            for (int nj2 = 0; nj2 < NJ / 2; nj2++) {
                uint32_t addr = hb + SWZ((uint32_t)((wn0 + nj2 * 16 + b_rowo) * 128 +
                                                    boff + k16 * 32 + b_csel));
                ldm_x4(bf[2 * nj2][0], bf[2 * nj2][1],
                       bf[2 * nj2 + 1][0], bf[2 * nj2 + 1][1], addr);
            }
            if (more) conv_range(par ^ 1, (TOT * sg) / NSG, (TOT * (sg + 1)) / NSG);
#pragma unroll
            for (int mi = 0; mi < 4; mi++)
#pragma unroll
                for (int nj = 0; nj < NJ; nj++)
                    mma16816(cacc[mi][nj][0], cacc[mi][nj][1],
                             cacc[mi][nj][2], cacc[mi][nj][3],
                             a[mi][0], a[mi][1], a[mi][2], a[mi][3],
                             bf[nj][0], bf[nj][1]);
        }
        if (more) __syncthreads();
    }

    const int rA = wm0 + (lid >> 2);
    const int lcol = wn0 + 2 * (lid & 3);
    if (mode == 0) {
#pragma unroll
        for (int mi = 0; mi < 4; mi++) {
#pragma unroll
            for (int nj = 0; nj < NJ; nj++) {
                int lc = lcol + nj * 8;
                int n = n0 + lc;
                if (n < Nrows) {
                    int r0r = row0 + rA + mi * 16;
                    float2 v0 = make_float2(cacc[mi][nj][0] + add_s[lc],
                                            cacc[mi][nj][1] + add_s[lc + 1]);
                    float2 v1 = make_float2(cacc[mi][nj][2] + add_s[lc],
                                            cacc[mi][nj][3] + add_s[lc + 1]);
                    *(float2*)&outS[(size_t)r0r * ldout + n] = v0;
                    *(float2*)&outS[(size_t)(r0r + 8) * ldout + n] = v1;
                }
            }
        }
    } else if (mode == 2) {
#pragma unroll
        for (int mi = 0; mi < 4; mi++) {
            float s0 = 0.f, s1 = 0.f;
#pragma unroll
            for (int nj = 0; nj < NJ; nj++) {
                int lc = lcol + nj * 8;
                int n = n0 + lc;
                if (n < Nrows) {
                    float e0 = __expf(cacc[mi][nj][0] + add_s[lc]);
                    float e1 = __expf(cacc[mi][nj][1] + add_s[lc + 1]);
                    float e2 = __expf(cacc[mi][nj][2] + add_s[lc]);
                    float e3 = __expf(cacc[mi][nj][3] + add_s[lc + 1]);
                    int r0r = row0 + rA + mi * 16;
                    *(float2*)&outS[(size_t)r0r * ldout + n] = make_float2(e0, e1);
                    *(float2*)&outS[(size_t)(r0r + 8) * ldout + n] = make_float2(e2, e3);
                    s0 += e0 + e1;
                    s1 += e2 + e3;
                }
            }
            s0 += __shfl_xor_sync(0xffffffffu, s0, 1);
            s0 += __shfl_xor_sync(0xffffffffu, s0, 2);
            s1 += __shfl_xor_sync(0xffffffffu, s1, 1);
            s1 += __shfl_xor_sync(0xffffffffu, s1, 2);
            if ((lid & 3) == 0) {
                atomicAdd(&outv[row0 + rA + mi * 16], s0);
                atomicAdd(&outv[row0 + rA + mi * 16 + 8], s1);
            }
        }
    } else {
#pragma unroll
        for (int mi = 0; mi < 4; mi++) {
            float p0 = 0.f, p1 = 0.f;
#pragma unroll
            for (int nj = 0; nj < NJ; nj++) {
                int lc = lcol + nj * 8;
                float ad0 = add_s[lc], ad1 = add_s[lc + 1];
                float w0 = wv_s[lc],  w1 = wv_s[lc + 1];
                p0 += fast_tanh(cacc[mi][nj][0] + ad0) * w0
                    + fast_tanh(cacc[mi][nj][1] + ad1) * w1;
                p1 += fast_tanh(cacc[mi][nj][2] + ad0) * w0
                    + fast_tanh(cacc[mi][nj][3] + ad1) * w1;
            }
            p0 += __shfl_xor_sync(0xffffffffu, p0, 1);
            p0 += __shfl_xor_sync(0xffffffffu, p0, 2);
            p1 += __shfl_xor_sync(0xffffffffu, p1, 1);
            p1 += __shfl_xor_sync(0xffffffffu, p1, 2);
            if ((lid & 3) == 0) {
                atomicAdd(&outv[row0 + rA + mi * 16], p0);
                atomicAdd(&outv[row0 + rA + mi * 16 + 8], p1);
            }
        }
    }
}

// ---- energy GEMM: NT=1 ----
__global__ __launch_bounds__(256)
void hmma_gemm8(const float* __restrict__ A, int lda, int K,
                const float* __restrict__ B, int ldb, int bcol, int Nrows,
                int mode,
                const float* __restrict__ addg, int add_per_b, int Ntot,
                const float* __restrict__ wvg, int wv_per_b,
                float* __restrict__ outS, int ldout,
                float* __restrict__ outv)
{
    extern __shared__ char smem_raw[];
    char* smem = (char*)(((uintptr_t)smem_raw + 1023) & ~(uintptr_t)1023);
    hmma_core8<1>(smem, A, lda, K, B, ldb, bcol, Nrows, mode,
                  addg, add_per_b, Ntot, wvg, wv_per_b, outS, ldout, outv,
                  blockIdx.x * 128, blockIdx.y * 256);
}

// ---- merged score_g(exp, NT=1) + score_c(NT=3) GEMM ----
#define NT_G 196
#define NT_C 1024
__global__ __launch_bounds__(256)
void hmma_scores(const float* __restrict__ yv,
                 const float* __restrict__ Wo, const float* __restrict__ Wob,
                 const float* __restrict__ enc,
                 const float* __restrict__ Wc, const float* __restrict__ Wcb,
                 float* __restrict__ scoregE, float* __restrict__ zrow,
                 float* __restrict__ scorec)
{
    extern __shared__ char smem_raw[];
    char* smem = (char*)(((uintptr_t)smem_raw + 1023) & ~(uintptr_t)1023);
    int tile = blockIdx.x;
    if (tile < NT_G) {
        hmma_core8<1>(smem, yv, 1024, 1024, Wo, 1024, 0, VV, 2,
                      Wob, 0, 0, nullptr, 0, scoregE, VV, zrow,
                      0, tile * 256);
    } else {
        int t2 = tile - NT_G;
        hmma_core8<3>(smem, enc, 512, 512, Wc, 512, 0, 1024, 1,
                      Wcb, 0, 1024, yv, 1, nullptr, 0, scorec,
                      (t2 >> 2) * 128, (t2 & 3) * 256);
    }
}

// ================= FFMA2 small GEMM =================
__device__ __forceinline__ void ffma2(unsigned long long &c,
                                      unsigned long long a,
                                      unsigned long long b) {
    asm("fma.rn.f32x2 %0, %1, %2, %0;" : "+l"(c) : "l"(a), "l"(b));
}
struct __align__(16) ull2 { unsigned long long x, y; };
__device__ __forceinline__ float f2lo(unsigned long long v) {
    return __uint_as_float((unsigned int)v);
}
__device__ __forceinline__ float f2hi(unsigned long long v) {
    return __uint_as_float((unsigned int)(v >> 32));
}
__device__ __forceinline__ unsigned long long dupf(float v) {
    unsigned int u = __float_as_uint(v);
    unsigned long long r;
    asm("mov.b64 %0, {%1, %1};" : "=l"(r) : "r"(u));
    return r;
}
#define K16_FFMA2_LOOP(acc, Asm, Wsm, ty, tx)                                 \
    _Pragma("unroll")                                                         \
    for (int kk = 0; kk < 16; kk++) {                                         \
        ull2 a01 = *(const ull2*)&Asm[kk][(ty) * 8];                          \
        ull2 a23 = *(const ull2*)&Asm[kk][(ty) * 8 + 4];                      \
        float4 wq = *(const float4*)&Wsm[kk][(tx) * 4];                       \
        unsigned long long w0 = dupf(wq.x), w1 = dupf(wq.y);                  \
        unsigned long long w2 = dupf(wq.z), w3 = dupf(wq.w);                  \
        ffma2(acc[0][0], a01.x, w0); ffma2(acc[0][1], a01.x, w1);             \
        ffma2(acc[0][2], a01.x, w2); ffma2(acc[0][3], a01.x, w3);             \
        ffma2(acc[1][0], a01.y, w0); ffma2(acc[1][1], a01.y, w1);             \
        ffma2(acc[1][2], a01.y, w2); ffma2(acc[1][3], a01.y, w3);             \
        ffma2(acc[2][0], a23.x, w0); ffma2(acc[2][1], a23.x, w1);             \
        ffma2(acc[2][2], a23.x, w2); ffma2(acc[2][3], a23.x, w3);             \
        ffma2(acc[3][0], a23.y, w0); ffma2(acc[3][1], a23.y, w1);             \
        ffma2(acc[3][2], a23.y, w2); ffma2(acc[3][3], a23.y, w3);             \
    }

__device__ __forceinline__ void gemm128_core(
    const float* __restrict__ A, int lda, const int* __restrict__ aidx,
    const float* __restrict__ W, int ldw, const float* __restrict__ bias,
    float* __restrict__ C, int N, int n0, int ks, int kl, bool addbias)
{
    __shared__ float Asm[16][132];
    __shared__ float Wsm[16][68];
    const int tid = threadIdx.x;
    const int ty = tid >> 4, tx = tid & 15;
    const int am  = tid >> 2;
    const int akv = (tid & 3) << 2;

    unsigned long long acc[4][4];
#pragma unroll
    for (int i = 0; i < 4; i++)
#pragma unroll
        for (int j = 0; j < 4; j++) acc[i][j] = 0ull;

    for (int k0 = ks; k0 < ks + kl; k0 += 16) {
        __syncthreads();
#pragma unroll
        for (int r = 0; r < 2; r++) {
            int m = am + r * 64;
            long arow = aidx ? (long)aidx[m] : (long)m;
            float4 v = *(const float4*)&A[arow * lda + k0 + akv];
            Asm[akv+0][m] = v.x; Asm[akv+1][m] = v.y;
            Asm[akv+2][m] = v.z; Asm[akv+3][m] = v.w;
        }
        {
            float4 v = *(const float4*)&W[(size_t)(n0 + am) * ldw + k0 + akv];
            Wsm[akv+0][am] = v.x; Wsm[akv+1][am] = v.y;
            Wsm[akv+2][am] = v.z; Wsm[akv+3][am] = v.w;
        }
        __syncthreads();
        K16_FFMA2_LOOP(acc, Asm, Wsm, ty, tx)
    }
#pragma unroll
    for (int r2 = 0; r2 < 4; r2++) {
#pragma unroll
        for (int j = 0; j < 4; j++) {
            int n = n0 + tx * 4 + j;
            float bsum = (addbias && bias) ? bias[n] : 0.f;
            int m0 = ty * 8 + 2 * r2;
            atomicAdd(&C[(size_t)m0 * N + n],       f2lo(acc[r2][j]) + bsum);
            atomicAdd(&C[(size_t)(m0 + 1) * N + n], f2hi(acc[r2][j]) + bsum);
        }
    }
}

__global__ __launch_bounds__(256)
void gemm128_splitk(const float* __restrict__ A, int lda,
                    const float* __restrict__ W, int ldw,
                    const float* __restrict__ bias,
                    float* __restrict__ C, int N, int Ktot)
{
    int kl = Ktot / gridDim.y;
    gemm128_core(A, lda, nullptr, W, ldw, bias, C, N,
                 blockIdx.x * 64, blockIdx.y * kl, kl, blockIdx.y == 0);
}

// merged: prev = prev_state@Ws^T + Ws_b  AND  gi = embed[idx]@Wih[:, :E]^T + bih
__global__ __launch_bounds__(256)
void gemm_chain1(const float* __restrict__ prev_state,
                 const float* __restrict__ Ws_w, const float* __restrict__ Ws_b,
                 float* __restrict__ prev,
                 const int* __restrict__ input_idx,
                 const float* __restrict__ embed_table,
                 const float* __restrict__ gru_Wih,
                 const float* __restrict__ gru_bih,
                 float* __restrict__ gi)
{
    int bx = blockIdx.x;
    if (bx < 64) {
        int n0 = (bx & 7) * 64, kb = bx >> 3;
        gemm128_core(prev_state, HH, nullptr, Ws_w, HH, Ws_b, prev, HH,
                     n0, kb * 64, 64, kb == 0);
    } else {
        bx -= 64;
        int n0 = (bx % 24) * 64, kb = bx / 24;
        gemm128_core(embed_table, EE, input_idx, gru_Wih, EE + HH, gru_bih,
                     gi, 3 * HH, n0, kb * 64, 64, kb == 0);
    }
}

// zero split-K accumulators + energy + scorec + zrow/invz/pcsum (float4)
__global__ __launch_bounds__(256)
void zero_all(float4* __restrict__ base, float4* __restrict__ energy,
              float4* __restrict__ scorec, float* __restrict__ tailz)
{
    int i = blockIdx.x * 256 + threadIdx.x;
    float4 z4 = make_float4(0.f, 0.f, 0.f, 0.f);
    if (i < NZ / 4) base[i] = z4;
    if (i < (BB * SS) / 4) { energy[i] = z4; scorec[i] = z4; }
    if (i < 2 * BB + 1) tailz[i] = 0.f;   // invz, zrow, pcsum
}

__global__ __launch_bounds__(256)
void gru_kernel(const float* __restrict__ gi, const float* __restrict__ gh,
                const float* __restrict__ prev,
                float* __restrict__ state, float* __restrict__ y,
                float* __restrict__ out_state)
{
    int i = blockIdx.x * 256 + threadIdx.x;
    int b = i / HH, h = i - b * HH;
    const float* gib = gi + b * 3 * HH;
    const float* ghb = gh + b * 3 * HH;
    float i_r = gib[h],          h_r = ghb[h];
    float i_z = gib[HH + h],     h_z = ghb[HH + h];
    float i_n = gib[2 * HH + h], h_n = ghb[2 * HH + h];
    float r = 1.f / (1.f + expf(-(i_r + h_r)));
    float z = 1.f / (1.f + expf(-(i_z + h_z)));
    float n = tanhf(i_n + r * h_n);
    float st = (1.f - z) * n + z * prev[i];
    state[i] = st;
    y[b * (2 * HH) + h] = st;
    out_state[i] = st;
}

// fused attention softmax + context
__global__ __launch_bounds__(512)
void softmax_context(const float* __restrict__ e, const float* __restrict__ enc,
                     float* __restrict__ y)
{
    int b = blockIdx.x, t = threadIdx.x;
    __shared__ float sm[256];
    __shared__ float c[256];
    float x = 0.f;
    if (t < 256) { x = e[b * SS + t]; sm[t] = x; }
    __syncthreads();
    for (int o = 128; o > 0; o >>= 1) {
        if (t < o) sm[t] = fmaxf(sm[t], sm[t + o]);
        __syncthreads();
    }
    float mx = sm[0];
    __syncthreads();
    float ex = 0.f;
    if (t < 256) { ex = expf(x - mx); sm[t] = ex; }
    __syncthreads();
    for (int o = 128; o > 0; o >>= 1) {
        if (t < o) sm[t] += sm[t + o];
        __syncthreads();
    }
    float Z = sm[0];
    __syncthreads();
    if (t < 256) c[t] = ex / Z;
    __syncthreads();
    float acc = 0.f;
    const float* eb = enc + (size_t)b * SS * HH + t;
#pragma unroll 4
    for (int s = 0; s < SS; s++) acc += c[s] * eb[s * HH];
    y[b * (2 * HH) + HH + t] = acc;
}

// finish Z with score_c exps; probc = ec/Z; invz; pcsum; scatter ec into E
__global__ __launch_bounds__(256)
void probc_z_kernel(const float* __restrict__ c, const int* __restrict__ eidx,
                    float* __restrict__ zrow, float* __restrict__ invz,
                    float* __restrict__ pc, float* __restrict__ pcsum,
                    float* __restrict__ E)
{
    int b = blockIdx.x, t = threadIdx.x;
    int e = eidx[b * SS + t];
    float x = c[b * SS + t] + ((e == 0) ? -1000.f : 0.f);
    float ec = __expf(x);
    atomicAdd(&E[(size_t)b * VV + e], ec);
    __shared__ float sm[256];
    __shared__ float iZs;
    sm[t] = ec; __syncthreads();
    for (int o = 128; o > 0; o >>= 1) { if (t < o) sm[t] += sm[t + o]; __syncthreads(); }
    if (t == 0) {
        float Z = zrow[b] + sm[0];
        float iZ = 1.f / Z;
        iZs = iZ;
        invz[b] = iZ;
        atomicAdd(pcsum, sm[0] * iZ);
    }
    __syncthreads();
    pc[b * SS + t] = ec * iZs;
}

// prob_g_ext write (float4): out = E * invZ
#define NW4 ((BB * VEXT) / 4)
#define ROW4 (VEXT / 4)
#define VV4  (VV / 4)
__global__ __launch_bounds__(256)
void finalize_kernel(const float4* __restrict__ E, const float* __restrict__ invz,
                     float4* __restrict__ out)
{
    int i = blockIdx.x * 256 + threadIdx.x;
    if (i >= NW4) return;
    int b = i / ROW4;
    int j4 = i - b * ROW4;
    if (j4 < VV4) {
        float iZ = invz[b];
        float4 v = E[(size_t)b * VV4 + j4];
        out[i] = make_float4(v.x * iZ, v.y * iZ, v.z * iZ, v.w * iZ);
    } else {
        out[i] = make_float4(1e-4f, 1e-4f, 1e-4f, 1e-4f);
    }
}

// weighted_new
__global__ __launch_bounds__(512)
void weighted_kernel(const int* __restrict__ eidx, const int* __restrict__ iidx,
                     const float* __restrict__ pc, const float* __restrict__ enc,
                     const float* __restrict__ pcsum, float* __restrict__ outw)
{
    int b = blockIdx.x, t = threadIdx.x;
    __shared__ float coef[256];
    __shared__ int cnt;
    if (t == 0) cnt = 0;
    __syncthreads();
    if (t < 256) {
        int match = (eidx[b * SS + t] == iidx[b]);
        coef[t] = match ? pc[b * SS + t] : 0.f;
        if (match) atomicAdd(&cnt, 1);
    }
    __syncthreads();
    float scale = 1.f / (*pcsum);
    if (cnt > 1) scale /= (float)cnt;
    float acc = 0.f;
    const float* eb = enc + (size_t)b * SS * HH + t;
#pragma unroll 4
    for (int s = 0; s < SS; s++) acc += coef[s] * eb[s * HH];
    outw[b * HH + t] = acc * scale;
}

// =========================== launch (single stream) ===========================
extern "C" void kernel_launch(void* const* d_in, const int* in_sizes, int n_in,
                              void* d_out, int out_size)
{
    const int*   input_idx   = (const int*)  d_in[0];
    const float* encoded     = (const float*)d_in[1];
    const int*   encoded_idx = (const int*)  d_in[2];
    const float* prev_state  = (const float*)d_in[3];
    const float* embed_table = (const float*)d_in[5];
    const float* Ws_w        = (const float*)d_in[6];
    const float* Ws_b        = (const float*)d_in[7];
    const float* gru_Wih     = (const float*)d_in[8];
    const float* gru_Whh     = (const float*)d_in[9];
    const float* gru_bih     = (const float*)d_in[10];
    const float* gru_bhh     = (const float*)d_in[11];
    const float* attn_W      = (const float*)d_in[12];
    const float* attn_b      = (const float*)d_in[13];
    const float* attn_v      = (const float*)d_in[14];
    const float* Wo_w        = (const float*)d_in[15];
    const float* Wo_b        = (const float*)d_in[16];
    const float* Wc_w        = (const float*)d_in[17];
    const float* Wc_b        = (const float*)d_in[18];

    float* out          = (float*)d_out;
    float* out_state    = out + (size_t)BB * VEXT;
    float* out_weighted = out_state + BB * HH;

    float* sc = nullptr;
    cudaGetSymbolAddress((void**)&sc, g_scratch);
    float* prev   = sc + OFF_PREV;
    float* gi     = sc + OFF_GI;
    float* gh     = sc + OFF_GH;
    float* satt   = sc + OFF_SATT;
    float* state  = sc + OFF_STATE;
    float* energy = sc + OFF_ENERGY;
    float* yv     = sc + OFF_Y;
    float* scoreg = sc + OFF_SCOREG;
    float* scorec = sc + OFF_SCOREC;
    float* probc  = sc + OFF_PROBC;
    float* invz   = sc + OFF_INVZ;
    float* zrow   = sc + OFF_Z;
    float* pcsum  = sc + OFF_PCSUM;

    cudaFuncSetAttribute(hmma_gemm8, cudaFuncAttributeMaxDynamicSharedMemorySize,
                         V4_DYN);
    cudaFuncSetAttribute(hmma_scores, cudaFuncAttributeMaxDynamicSharedMemorySize,
                         V4_DYN);

    // 1. all zeroing in one launch (float4)
    zero_all<<<(NZ / 4 + 255) / 256, 256>>>((float4*)prev, (float4*)energy,
                                            (float4*)scorec, invz);
    // 2. prev + gi merged (gather fused into gi A-load)
    gemm_chain1<<<64 + 192, 256>>>(prev_state, Ws_w, Ws_b, prev,
                                   input_idx, embed_table, gru_Wih, gru_bih, gi);
    // 3. gh
    gemm128_splitk<<<dim3(3 * HH / 64, 8), 256>>>(prev, HH, gru_Whh, HH,
                                                  gru_bhh, gh, 3 * HH, HH);
    // 4. GRU
    gru_kernel<<<(BB * HH) / 256, 256>>>(gi, gh, prev, state, yv, out_state);
    // 5. satt
    gemm128_splitk<<<dim3(HH / 64, 8), 256>>>(state, HH, attn_W, 2 * HH,
                                              attn_b, satt, HH, HH);
    // 6. energy GEMM (NT=1)
    hmma_gemm8<<<dim3(256, 2), 256, V4_DYN>>>(
        encoded, 512, 512,
        attn_W, 1024, 512, 512,
        1, satt, 1, 512, attn_v, 0,
        nullptr, 0, energy);
    // 7. attention softmax + context
    softmax_context<<<BB, 512>>>(energy, encoded, yv);
    // 8. merged score_g (NT=1, exp epilogue) + score_c (NT=3)
    hmma_scores<<<NT_G + NT_C, 256, V4_DYN>>>(
        yv, Wo_w, Wo_b, encoded, Wc_w, Wc_b, scoreg, zrow, scorec);
    // 9. finish Z; probc; invz; pcsum; scatter ec into E
    probc_z_kernel<<<BB, SS>>>(scorec, encoded_idx, zrow, invz, probc, pcsum,
                               scoreg);
    // 10. prob_g_ext + scattered copy probs, one vectorized multiply
    finalize_kernel<<<(NW4 + 255) / 256, 256>>>((const float4*)scoreg, invz,
                                                (float4*)out);
    // 11. weighted_new
    weighted_kernel<<<BB, 512>>>(encoded_idx, input_idx, probc, encoded,
                                 pcsum, out_weighted);
}